// round 1
// baseline (speedup 1.0000x reference)
#include <cuda_runtime.h>
#include <cstdint>

#define EGO   64
#define MEM   128
#define NOBJ  20
#define HW    65536     // 256*256
#define NPIX  131072    // 2 * HW
#define NB    2
#define TT    4

// ---------------- static scratch (no allocations allowed) ----------------
__device__ float g_state_a[(size_t)NPIX * MEM];        // 64 MB
__device__ float g_state_b[(size_t)NPIX * MEM];        // 64 MB
__device__ float g_bufA[(size_t)NB * 128 * HW];        // 64 MB
__device__ float g_bufB[(size_t)NB * 128 * HW];        // 64 MB
__device__ int   g_any[8];
__device__ float g_stats[256];    // [0..C) sum, [128..128+C) sumsq
__device__ float g_scale[128];
__device__ float g_shift[128];

// ---------------- any(mask) per (n,t) ----------------
__global__ void any_kernel(const int* __restrict__ masks) {
    int idx = blockIdx.x * blockDim.x + threadIdx.x;   // < 524288
    int v = masks[idx];
    unsigned b = __ballot_sync(0xffffffffu, v > 0);
    if ((threadIdx.x & 31) == 0 && b)
        atomicOr(&g_any[idx >> 16], 1);
}

// ---------------- observed_masks ----------------
__global__ void obs_kernel(const int* __restrict__ masks, float* __restrict__ outobs) {
    int idx = blockIdx.x * blockDim.x + threadIdx.x;   // < 131072
    int n = idx >> 16, pix = idx & 65535;
    int s = 0;
#pragma unroll
    for (int t = 0; t < TT; ++t)
        s += masks[((n * TT + t) << 16) + pix] * g_any[n * TT + t];
    outobs[idx] = (float)s;
}

// ---------------- GRU step (GEMM-style) ----------------
// block: 256 thr = 16 units x 16 pixel-groups(8 px). tile: 128 px, 16 units (48 gate rows)
// grid: (1024, 8)
__global__ __launch_bounds__(256) void gru_step(
    const float* __restrict__ feats, const int* __restrict__ masks,
    const float* __restrict__ w_ih, const float* __restrict__ w_hh,
    const float* __restrict__ b_ih, const float* __restrict__ b_hh,
    const float* __restrict__ hin, float* __restrict__ hout, int t)
{
    __shared__ __align__(16) float it[16 * 132];   // [k][px] padded
    __shared__ float wt[16 * 49];                  // [k][g*16+u] padded

    int tid = threadIdx.x;
    int u  = tid & 15;
    int pg = tid >> 4;
    int ub = blockIdx.y * 16, uc = ub + u;
    int p0 = blockIdx.x * 128;
    int n = p0 >> 16;
    int pix0 = p0 & 65535;

    const float* fbase = feats + ((size_t)(n * TT + t) * HW + pix0) * EGO;
    const float* hbase = hin + (size_t)p0 * MEM;

    float ar[8], az[8], ax[8], ah[8];
#pragma unroll
    for (int j = 0; j < 8; ++j) { ar[j] = az[j] = ax[j] = ah[j] = 0.f; }

    int lp = tid >> 1;          // staging pixel 0..127
    int kh = (tid & 1) * 8;     // staging k offset

    for (int c = 0; c < 12; ++c) {
        int kb = c * 16;
        __syncthreads();
        { // stage inputs: 16k x 128px, coalesced along channel dim
            const float* src = (kb < 64) ? (fbase + (size_t)lp * EGO + kb + kh)
                                         : (hbase + (size_t)lp * MEM + (kb - 64) + kh);
            float4 v0 = *(const float4*)src;
            float4 v1 = *(const float4*)(src + 4);
            it[(kh + 0) * 132 + lp] = v0.x; it[(kh + 1) * 132 + lp] = v0.y;
            it[(kh + 2) * 132 + lp] = v0.z; it[(kh + 3) * 132 + lp] = v0.w;
            it[(kh + 4) * 132 + lp] = v1.x; it[(kh + 5) * 132 + lp] = v1.y;
            it[(kh + 6) * 132 + lp] = v1.z; it[(kh + 7) * 132 + lp] = v1.w;
        }
        // stage weights: 48 rows x 16 k
#pragma unroll
        for (int q = 0; q < 3; ++q) {
            int idx = tid + q * 256;
            int row = idx >> 4, kl = idx & 15;
            int g = row >> 4, uu = row & 15;
            int grow = g * 128 + ub + uu;
            float val = (kb < 64) ? w_ih[grow * 64 + kb + kl]
                                  : w_hh[grow * 128 + (kb - 64) + kl];
            wt[kl * 49 + row] = val;
        }
        __syncthreads();

        int px = pg * 8;
        if (c < 4) {
#pragma unroll
            for (int k = 0; k < 16; ++k) {
                float wr = wt[k * 49 + u];
                float wz = wt[k * 49 + 16 + u];
                float wn = wt[k * 49 + 32 + u];
                float4 i0 = *(const float4*)&it[k * 132 + px];
                float4 i1 = *(const float4*)&it[k * 132 + px + 4];
                float xi[8] = { i0.x, i0.y, i0.z, i0.w, i1.x, i1.y, i1.z, i1.w };
#pragma unroll
                for (int j = 0; j < 8; ++j) {
                    ar[j] += wr * xi[j];
                    az[j] += wz * xi[j];
                    ax[j] += wn * xi[j];
                }
            }
        } else {
#pragma unroll
            for (int k = 0; k < 16; ++k) {
                float wr = wt[k * 49 + u];
                float wz = wt[k * 49 + 16 + u];
                float wn = wt[k * 49 + 32 + u];
                float4 i0 = *(const float4*)&it[k * 132 + px];
                float4 i1 = *(const float4*)&it[k * 132 + px + 4];
                float xi[8] = { i0.x, i0.y, i0.z, i0.w, i1.x, i1.y, i1.z, i1.w };
#pragma unroll
                for (int j = 0; j < 8; ++j) {
                    ar[j] += wr * xi[j];
                    az[j] += wz * xi[j];
                    ah[j] += wn * xi[j];
                }
            }
        }
    }

    // epilogue: gates + masked state update
    float bir = b_ih[uc], biz = b_ih[128 + uc], bin_ = b_ih[256 + uc];
    float bhr = b_hh[uc], bhz = b_hh[128 + uc], bhn = b_hh[256 + uc];
    const int* mrow = masks + ((size_t)(n * TT + t) << 16);
#pragma unroll
    for (int j = 0; j < 8; ++j) {
        int p = p0 + pg * 8 + j;
        int pix = pix0 + pg * 8 + j;
        float hu = hin[(size_t)p * MEM + uc];
        float r = 1.f / (1.f + __expf(-(ar[j] + bir + bhr)));
        float z = 1.f / (1.f + __expf(-(az[j] + biz + bhz)));
        float nn = tanhf(ax[j] + bin_ + r * (ah[j] + bhn));
        float hnew = (1.f - z) * nn + z * hu;
        hout[(size_t)p * MEM + uc] = (mrow[pix] > 0) ? hnew : hu;
    }
}

// ---------------- NHWC -> NCHW transpose ----------------
__global__ void transpose_kernel(const float* __restrict__ in, float* __restrict__ out) {
    __shared__ float tile[32][33];
    int n = blockIdx.z;
    int p0 = blockIdx.x * 32;
    int c0 = blockIdx.y * 32;
    int tx = threadIdx.x, ty = threadIdx.y;   // (32, 8)
#pragma unroll
    for (int i = 0; i < 32; i += 8)
        tile[ty + i][tx] = in[((size_t)(n * HW + p0 + ty + i)) * MEM + c0 + tx];
    __syncthreads();
#pragma unroll
    for (int i = 0; i < 32; i += 8)
        out[((size_t)(n * 128 + c0 + ty + i)) * HW + p0 + tx] = tile[tx][ty + i];
}

// ---------------- direct conv + BN-stat accumulation ----------------
// block: 256 thr, tile 64 oc x 128 px (one row segment). thread: 4 oc x 8 px.
// grid: (512, ceil(Cout/64), 2)
template<int K>
__global__ __launch_bounds__(256) void conv_kernel(
    const float* __restrict__ in, const float* __restrict__ w,
    float* __restrict__ out, int Cin, int Cout)
{
    constexpr int PAD  = K / 2;
    constexpr int ICB  = (K == 7) ? 2 : 8;
    constexpr int WRAW = 128 + 2 * PAD;
    constexpr int WIN  = (WRAW + 3) & ~3;
    constexpr int RTOT = ICB * K * K;

    __shared__ float itile[ICB * K * WIN];
    __shared__ __align__(16) float wtile[RTOT * 68];
    __shared__ float sacc[64], qacc[64];

    int tid = threadIdx.x;
    int ocg = tid & 15, pxg = tid >> 4;
    int oc_l = ocg * 4, px_l = pxg * 8;
    int bx = blockIdx.x;
    int x0 = (bx & 1) * 128, y = bx >> 1;
    int ocb = blockIdx.y * 64;
    int n = blockIdx.z;

    if (tid < 64) { sacc[tid] = 0.f; qacc[tid] = 0.f; }

    float acc[4][8];
#pragma unroll
    for (int i = 0; i < 4; ++i)
#pragma unroll
        for (int j = 0; j < 8; ++j) acc[i][j] = 0.f;

    for (int ic0 = 0; ic0 < Cin; ic0 += ICB) {
        __syncthreads();
        // stage input rows (zero-padded borders)
        for (int idx = tid; idx < ICB * K * WIN; idx += 256) {
            int icl = idx / (K * WIN);
            int rem = idx - icl * (K * WIN);
            int ky = rem / WIN, xx = rem - ky * WIN;
            int gy = y + ky - PAD, gx = x0 + xx - PAD;
            float v = 0.f;
            if (xx < WRAW && (unsigned)gy < 256u && (unsigned)gx < 256u)
                v = in[((size_t)((n * Cin + ic0 + icl) * 256 + gy) << 8) + gx];
            itile[idx] = v;
        }
        // stage weights (coalesced per-oc runs, transposed to [r][oc])
        const float* wb = w + (size_t)ic0 * K * K;
        for (int idx = tid; idx < RTOT * 64; idx += 256) {
            int ol = idx / RTOT;
            int r  = idx - ol * RTOT;
            int oc = ocb + ol;
            float v = (oc < Cout) ? wb[(size_t)oc * Cin * K * K + r] : 0.f;
            wtile[r * 68 + ol] = v;
        }
        __syncthreads();

#pragma unroll
        for (int icl = 0; icl < ICB; ++icl)
#pragma unroll
        for (int ky = 0; ky < K; ++ky) {
            const float* irow = &itile[(icl * K + ky) * WIN + px_l];
            float rin[8 + K - 1];
#pragma unroll
            for (int j = 0; j < 8 + K - 1; ++j) rin[j] = irow[j];
#pragma unroll
            for (int kx = 0; kx < K; ++kx) {
                float4 wv = *(const float4*)&wtile[((icl * K + ky) * K + kx) * 68 + oc_l];
#pragma unroll
                for (int j = 0; j < 8; ++j) {
                    acc[0][j] += wv.x * rin[j + kx];
                    acc[1][j] += wv.y * rin[j + kx];
                    acc[2][j] += wv.z * rin[j + kx];
                    acc[3][j] += wv.w * rin[j + kx];
                }
            }
        }
    }

    // store outputs + per-block BN partial sums
#pragma unroll
    for (int i = 0; i < 4; ++i) {
        int oc = ocb + oc_l + i;
        if (oc < Cout) {
            float* op = out + ((size_t)((n * Cout + oc) * 256 + y) << 8) + x0 + px_l;
            float4 v0 = { acc[i][0], acc[i][1], acc[i][2], acc[i][3] };
            float4 v1 = { acc[i][4], acc[i][5], acc[i][6], acc[i][7] };
            *(float4*)op = v0;
            *(float4*)(op + 4) = v1;
            float s = 0.f, q = 0.f;
#pragma unroll
            for (int j = 0; j < 8; ++j) { s += acc[i][j]; q += acc[i][j] * acc[i][j]; }
            atomicAdd(&sacc[oc_l + i], s);
            atomicAdd(&qacc[oc_l + i], q);
        }
    }
    __syncthreads();
    if (tid < 64 && (ocb + tid) < Cout) {
        atomicAdd(&g_stats[ocb + tid], sacc[tid]);
        atomicAdd(&g_stats[128 + ocb + tid], qacc[tid]);
    }
}

// ---------------- BN finalize + fused bn-relu ----------------
__global__ void bnfin_kernel(const float* __restrict__ g, const float* __restrict__ b, int C) {
    int c = threadIdx.x;
    if (c < C) {
        float inv = 1.f / (float)NPIX;
        float mu  = g_stats[c] * inv;
        float var = g_stats[128 + c] * inv - mu * mu;
        float sc  = g[c] * rsqrtf(var + 1e-5f);
        g_scale[c] = sc;
        g_shift[c] = b[c] - mu * sc;
    }
}

__global__ void bnrelu_kernel(float* __restrict__ x, int C) {
    int idx = blockIdx.x * 256 + threadIdx.x;
    int c = (idx >> 16) % C;
    float v = x[idx] * g_scale[c] + g_shift[c];
    x[idx] = fmaxf(v, 0.f);
}

// ---------------- final 1x1 conv (48 -> 20) + bias ----------------
__global__ __launch_bounds__(256) void obj2_kernel(
    const float* __restrict__ in, const float* __restrict__ w,
    const float* __restrict__ b, float* __restrict__ out)
{
    __shared__ float ws[NOBJ * 48];
    __shared__ float bs[NOBJ];
    int tid = threadIdx.x;
    for (int i = tid; i < NOBJ * 48; i += 256) ws[i] = w[i];
    if (tid < NOBJ) bs[tid] = b[tid];
    __syncthreads();

    int p = blockIdx.x * 256 + tid;
    int n = p >> 16, pix = p & 65535;
    float acc[NOBJ];
#pragma unroll
    for (int o = 0; o < NOBJ; ++o) acc[o] = bs[o];
    for (int ic = 0; ic < 48; ++ic) {
        float v = in[((size_t)(n * 48 + ic) << 16) + pix];
#pragma unroll
        for (int o = 0; o < NOBJ; ++o) acc[o] += ws[o * 48 + ic] * v;
    }
#pragma unroll
    for (int o = 0; o < NOBJ; ++o)
        out[((size_t)(n * NOBJ + o) << 16) + pix] = acc[o];
}

// ---------------- launch ----------------
extern "C" void kernel_launch(void* const* d_in, const int* in_sizes, int n_in,
                              void* d_out, int out_size)
{
    const float* feats  = (const float*)d_in[0];
    const int*   masks  = (const int*)  d_in[1];
    const float* w_ih   = (const float*)d_in[2];
    const float* w_hh   = (const float*)d_in[3];
    const float* b_ih   = (const float*)d_in[4];
    const float* b_hh   = (const float*)d_in[5];
    const float* conv1w = (const float*)d_in[6];
    const float* bn1g   = (const float*)d_in[7];
    const float* bn1b   = (const float*)d_in[8];
    const float* conv2w = (const float*)d_in[9];
    const float* bn2g   = (const float*)d_in[10];
    const float* bn2b   = (const float*)d_in[11];
    const float* conv3w = (const float*)d_in[12];
    const float* bn3g   = (const float*)d_in[13];
    const float* bn3b   = (const float*)d_in[14];
    const float* obj1w  = (const float*)d_in[15];
    const float* bn4g   = (const float*)d_in[16];
    const float* bn4b   = (const float*)d_in[17];
    const float* obj2w  = (const float*)d_in[18];
    const float* obj2b  = (const float*)d_in[19];
    float* out = (float*)d_out;

    void *pa, *pb, *pany, *pstats, *pbA, *pbB;
    cudaGetSymbolAddress(&pa, g_state_a);
    cudaGetSymbolAddress(&pb, g_state_b);
    cudaGetSymbolAddress(&pany, g_any);
    cudaGetSymbolAddress(&pstats, g_stats);
    cudaGetSymbolAddress(&pbA, g_bufA);
    cudaGetSymbolAddress(&pbB, g_bufB);
    float* sA = (float*)pa;
    float* sB = (float*)pb;
    float* bA = (float*)pbA;
    float* bB = (float*)pbB;

    cudaMemsetAsync(pa, 0, sizeof(g_state_a));
    cudaMemsetAsync(pany, 0, sizeof(g_any));

    any_kernel<<<2048, 256>>>(masks);
    obs_kernel<<<512, 256>>>(masks, out + (size_t)NB * NOBJ * HW);

    dim3 ggrid(1024, 8);
    gru_step<<<ggrid, 256>>>(feats, masks, w_ih, w_hh, b_ih, b_hh, sA, sB, 0);
    gru_step<<<ggrid, 256>>>(feats, masks, w_ih, w_hh, b_ih, b_hh, sB, sA, 1);
    gru_step<<<ggrid, 256>>>(feats, masks, w_ih, w_hh, b_ih, b_hh, sA, sB, 2);
    gru_step<<<ggrid, 256>>>(feats, masks, w_ih, w_hh, b_ih, b_hh, sB, sA, 3);

    transpose_kernel<<<dim3(2048, 4, 2), dim3(32, 8)>>>(sA, bA);

    // conv1 7x7 128->128
    cudaMemsetAsync(pstats, 0, sizeof(g_stats));
    conv_kernel<7><<<dim3(512, 2, 2), 256>>>(bA, conv1w, bB, 128, 128);
    bnfin_kernel<<<1, 128>>>(bn1g, bn1b, 128);
    bnrelu_kernel<<<128 * 512, 256>>>(bB, 128);

    // conv2 3x3 128->64
    cudaMemsetAsync(pstats, 0, sizeof(g_stats));
    conv_kernel<3><<<dim3(512, 1, 2), 256>>>(bB, conv2w, bA, 128, 64);
    bnfin_kernel<<<1, 128>>>(bn2g, bn2b, 64);
    bnrelu_kernel<<<64 * 512, 256>>>(bA, 64);

    // conv3 3x3 64->48
    cudaMemsetAsync(pstats, 0, sizeof(g_stats));
    conv_kernel<3><<<dim3(512, 1, 2), 256>>>(bA, conv3w, bB, 64, 48);
    bnfin_kernel<<<1, 128>>>(bn3g, bn3b, 48);
    bnrelu_kernel<<<48 * 512, 256>>>(bB, 48);

    // obj1 3x3 48->48
    cudaMemsetAsync(pstats, 0, sizeof(g_stats));
    conv_kernel<3><<<dim3(512, 1, 2), 256>>>(bB, obj1w, bA, 48, 48);
    bnfin_kernel<<<1, 128>>>(bn4g, bn4b, 48);
    bnrelu_kernel<<<48 * 512, 256>>>(bA, 48);

    // obj2 1x1 48->20 + bias
    obj2_kernel<<<512, 256>>>(bA, obj2w, obj2b, out);
}

// round 2
// speedup vs baseline: 1.1934x; 1.1934x over previous
#include <cuda_runtime.h>
#include <cstdint>

#define EGO   64
#define MEM   128
#define NOBJ  20
#define HW    65536     // 256*256
#define NPIX  131072    // 2 * HW
#define NB    2
#define TT    4

typedef unsigned long long u64;

// ---------------- packed f32x2 helpers (sm_103a dual-rate FMA) ----------------
__device__ __forceinline__ u64 bcast2(float x) {
    u64 r; asm("mov.b64 %0, {%1, %1};" : "=l"(r) : "f"(x)); return r;
}
__device__ __forceinline__ u64 pack2f(float x, float y) {
    u64 r; asm("mov.b64 %0, {%1, %2};" : "=l"(r) : "f"(x), "f"(y)); return r;
}
__device__ __forceinline__ u64 ffma2(u64 a, u64 b, u64 c) {
    u64 d; asm("fma.rn.f32x2 %0, %1, %2, %3;" : "=l"(d) : "l"(a), "l"(b), "l"(c)); return d;
}
__device__ __forceinline__ float2 unpk(u64 a) {
    float2 f; asm("mov.b64 {%0, %1}, %2;" : "=f"(f.x), "=f"(f.y) : "l"(a)); return f;
}

// ---------------- static scratch ----------------
__device__ float g_state_a[(size_t)NPIX * MEM];
__device__ float g_state_b[(size_t)NPIX * MEM];
__device__ float g_bufA[(size_t)NB * 128 * HW];
__device__ float g_bufB[(size_t)NB * 128 * HW];
__device__ int   g_any[8];
__device__ float g_stats[256];
__device__ float g_scale[128];
__device__ float g_shift[128];

// ---------------- any(mask) per (n,t) ----------------
__global__ void any_kernel(const int* __restrict__ masks) {
    int idx = blockIdx.x * blockDim.x + threadIdx.x;
    int v = masks[idx];
    unsigned b = __ballot_sync(0xffffffffu, v > 0);
    if ((threadIdx.x & 31) == 0 && b)
        atomicOr(&g_any[idx >> 16], 1);
}

// ---------------- observed_masks ----------------
__global__ void obs_kernel(const int* __restrict__ masks, float* __restrict__ outobs) {
    int idx = blockIdx.x * blockDim.x + threadIdx.x;
    int n = idx >> 16, pix = idx & 65535;
    int s = 0;
#pragma unroll
    for (int t = 0; t < TT; ++t)
        s += masks[((n * TT + t) << 16) + pix] * g_any[n * TT + t];
    outobs[idx] = (float)s;
}

// ---------------- GRU step: 32 units x 128 px tile, 2 units x 8 px / thread ----
// grid (1024, 4), 256 threads
template<bool FIRST, bool NCHW>
__global__ __launch_bounds__(256) void gru_step(
    const float* __restrict__ feats, const int* __restrict__ masks,
    const float* __restrict__ w_ih, const float* __restrict__ w_hh,
    const float* __restrict__ b_ih, const float* __restrict__ b_hh,
    const float* __restrict__ hin, float* __restrict__ hout, int t)
{
    __shared__ __align__(16) float it[16 * 132];   // [k][px]
    __shared__ __align__(16) float wt[16 * 100];   // [k][gate*32+unit]

    int tid = threadIdx.x;
    int u2 = tid & 15;       // unit-pair index
    int pg = tid >> 4;       // pixel group
    int ub = blockIdx.y * 32;
    int p0 = blockIdx.x * 128;
    int n = p0 >> 16, pix0 = p0 & 65535;
    int px = pg * 8;

    const float* fbase = feats + ((size_t)(n * TT + t) * HW + pix0) * EGO;
    const float* hbase = hin + (size_t)p0 * MEM;

    u64 ar[2][4], az[2][4], ax[2][4], ah[2][4];
#pragma unroll
    for (int un = 0; un < 2; ++un)
#pragma unroll
        for (int j = 0; j < 4; ++j) { ar[un][j] = az[un][j] = ax[un][j] = ah[un][j] = 0ull; }

    int lp = tid >> 1;
    int kh = (tid & 1) * 8;
    const int CMAX = FIRST ? 4 : 12;

    for (int c = 0; c < CMAX; ++c) {
        int kb = c * 16;
        __syncthreads();
        { // stage inputs transposed to [k][px]
            const float* src = (kb < 64) ? (fbase + (size_t)lp * EGO + kb + kh)
                                         : (hbase + (size_t)lp * MEM + (kb - 64) + kh);
            float4 v0 = *(const float4*)src;
            float4 v1 = *(const float4*)(src + 4);
            it[(kh + 0) * 132 + lp] = v0.x; it[(kh + 1) * 132 + lp] = v0.y;
            it[(kh + 2) * 132 + lp] = v0.z; it[(kh + 3) * 132 + lp] = v0.w;
            it[(kh + 4) * 132 + lp] = v1.x; it[(kh + 5) * 132 + lp] = v1.y;
            it[(kh + 6) * 132 + lp] = v1.z; it[(kh + 7) * 132 + lp] = v1.w;
        }
        // stage weights: 16k x (3 gates x 32 units) = 1536 = 256*6
#pragma unroll
        for (int q = 0; q < 6; ++q) {
            int idx = tid + q * 256;
            int kl = idx / 96;
            int row = idx - kl * 96;          // g*32+uu
            int g = row >> 5, uu = row & 31;
            int grow = g * 128 + ub + uu;
            float val = (kb < 64) ? w_ih[grow * 64 + kb + kl]
                                  : w_hh[grow * 128 + (kb - 64) + kl];
            wt[kl * 100 + row] = val;
        }
        __syncthreads();

#pragma unroll
        for (int k = 0; k < 16; ++k) {
            const float* wrow = &wt[k * 100];
            float2 wr = *(const float2*)&wrow[0  + 2 * u2];
            float2 wz = *(const float2*)&wrow[32 + 2 * u2];
            float2 wn = *(const float2*)&wrow[64 + 2 * u2];
            u64 wrp[2] = { bcast2(wr.x), bcast2(wr.y) };
            u64 wzp[2] = { bcast2(wz.x), bcast2(wz.y) };
            u64 wnp[2] = { bcast2(wn.x), bcast2(wn.y) };
            ulonglong2 x01 = *(const ulonglong2*)&it[k * 132 + px];
            ulonglong2 x23 = *(const ulonglong2*)&it[k * 132 + px + 4];
            u64 xi[4] = { x01.x, x01.y, x23.x, x23.y };
            if (c < 4) {
#pragma unroll
                for (int un = 0; un < 2; ++un)
#pragma unroll
                    for (int j = 0; j < 4; ++j) {
                        ar[un][j] = ffma2(wrp[un], xi[j], ar[un][j]);
                        az[un][j] = ffma2(wzp[un], xi[j], az[un][j]);
                        ax[un][j] = ffma2(wnp[un], xi[j], ax[un][j]);
                    }
            } else {
#pragma unroll
                for (int un = 0; un < 2; ++un)
#pragma unroll
                    for (int j = 0; j < 4; ++j) {
                        ar[un][j] = ffma2(wrp[un], xi[j], ar[un][j]);
                        az[un][j] = ffma2(wzp[un], xi[j], az[un][j]);
                        ah[un][j] = ffma2(wnp[un], xi[j], ah[un][j]);
                    }
            }
        }
    }

    // epilogue
    const int* mrow = masks + ((size_t)(n * TT + t) << 16) + pix0 + px;
    int mk[8];
#pragma unroll
    for (int j = 0; j < 8; ++j) mk[j] = mrow[j];

#pragma unroll
    for (int un = 0; un < 2; ++un) {
        int uc = ub + u2 * 2 + un;
        float bir = b_ih[uc], biz = b_ih[128 + uc], bin_ = b_ih[256 + uc];
        float bhr = b_hh[uc], bhz = b_hh[128 + uc], bhn = b_hh[256 + uc];
        float hh[8];
#pragma unroll
        for (int jp = 0; jp < 4; ++jp) {
            float2 fr = unpk(ar[un][jp]), fz = unpk(az[un][jp]);
            float2 fx = unpk(ax[un][jp]), fh = unpk(ah[un][jp]);
            float rr[2] = { fr.x, fr.y }, zz[2] = { fz.x, fz.y };
            float xx[2] = { fx.x, fx.y }, hp[2] = { fh.x, fh.y };
#pragma unroll
            for (int e = 0; e < 2; ++e) {
                int j = jp * 2 + e;
                float hu = FIRST ? 0.f : hin[(size_t)(p0 + px + j) * MEM + uc];
                float r = 1.f / (1.f + __expf(-(rr[e] + bir + bhr)));
                float z = 1.f / (1.f + __expf(-(zz[e] + biz + bhz)));
                float nn = tanhf(xx[e] + bin_ + r * (hp[e] + bhn));
                float hv = (1.f - z) * nn + z * hu;
                hh[j] = (mk[j] > 0) ? hv : hu;
            }
        }
        if (NCHW) {
            float* op = hout + (((size_t)(n * 128 + uc)) << 16) + pix0 + px;
            *(float4*)op       = make_float4(hh[0], hh[1], hh[2], hh[3]);
            *(float4*)(op + 4) = make_float4(hh[4], hh[5], hh[6], hh[7]);
        } else {
#pragma unroll
            for (int j = 0; j < 8; ++j)
                hout[(size_t)(p0 + px + j) * MEM + uc] = hh[j];
        }
    }
}

// ---------------- direct conv (f32x2) + BN-stat accumulation + fused input BN-relu
// block: 256 thr, tile 64 oc x 128 px. thread: 4 oc (2 f32x2 pairs) x 8 px.
template<int K, bool FUSE>
__global__ __launch_bounds__(256) void conv_kernel(
    const float* __restrict__ in, const float* __restrict__ w,
    float* __restrict__ out, int Cin, int Cout)
{
    constexpr int PAD  = K / 2;
    constexpr int ICB  = (K == 7) ? 2 : 8;
    constexpr int WRAW = 128 + 2 * PAD;
    constexpr int WIN  = (WRAW + 3) & ~3;
    constexpr int RTOT = ICB * K * K;

    __shared__ float itile[ICB * K * WIN];
    __shared__ __align__(16) float wtile[RTOT * 68];
    __shared__ float sacc[64], qacc[64];

    int tid = threadIdx.x;
    int ocg = tid & 15, pxg = tid >> 4;
    int oc_l = ocg * 4, px_l = pxg * 8;
    int bx = blockIdx.x;
    int x0 = (bx & 1) * 128, y = bx >> 1;
    int ocb = blockIdx.y * 64;
    int n = blockIdx.z;

    if (tid < 64) { sacc[tid] = 0.f; qacc[tid] = 0.f; }

    u64 accp0[8], accp1[8];
#pragma unroll
    for (int j = 0; j < 8; ++j) { accp0[j] = 0ull; accp1[j] = 0ull; }

    for (int ic0 = 0; ic0 < Cin; ic0 += ICB) {
        __syncthreads();
        // stage inputs (zero-padded, optional fused bn+relu)
        for (int idx = tid; idx < ICB * K * WIN; idx += 256) {
            int icl = idx / (K * WIN);
            int rem = idx - icl * (K * WIN);
            int ky = rem / WIN, xx = rem - ky * WIN;
            int gy = y + ky - PAD, gx = x0 + xx - PAD;
            float v = 0.f;
            if (xx < WRAW && (unsigned)gy < 256u && (unsigned)gx < 256u) {
                int c = ic0 + icl;
                v = in[((size_t)((n * Cin + c) * 256 + gy) << 8) + gx];
                if (FUSE) v = fmaxf(v * g_scale[c] + g_shift[c], 0.f);
            }
            itile[idx] = v;
        }
        // stage weights transposed to [r][oc]
        const float* wb = w + (size_t)ic0 * K * K;
        for (int idx = tid; idx < RTOT * 64; idx += 256) {
            int ol = idx / RTOT;
            int r  = idx - ol * RTOT;
            int oc = ocb + ol;
            float v = (oc < Cout) ? wb[(size_t)oc * Cin * K * K + r] : 0.f;
            wtile[r * 68 + ol] = v;
        }
        __syncthreads();

#pragma unroll
        for (int icl = 0; icl < ICB; ++icl)
#pragma unroll
        for (int ky = 0; ky < K; ++ky) {
            const float* irow = &itile[(icl * K + ky) * WIN + px_l];
            u64 rb[8 + K - 1];
#pragma unroll
            for (int j = 0; j < 8 + K - 1; ++j) rb[j] = bcast2(irow[j]);
#pragma unroll
            for (int kx = 0; kx < K; ++kx) {
                ulonglong2 wp = *(const ulonglong2*)&wtile[((icl * K + ky) * K + kx) * 68 + oc_l];
#pragma unroll
                for (int j = 0; j < 8; ++j) {
                    accp0[j] = ffma2(wp.x, rb[j + kx], accp0[j]);
                    accp1[j] = ffma2(wp.y, rb[j + kx], accp1[j]);
                }
            }
        }
    }

    // unpack
    float acc[4][8];
#pragma unroll
    for (int j = 0; j < 8; ++j) {
        float2 a0 = unpk(accp0[j]), a1 = unpk(accp1[j]);
        acc[0][j] = a0.x; acc[1][j] = a0.y; acc[2][j] = a1.x; acc[3][j] = a1.y;
    }

#pragma unroll
    for (int i = 0; i < 4; ++i) {
        int oc = ocb + oc_l + i;
        if (oc < Cout) {
            float* op = out + ((size_t)((n * Cout + oc) * 256 + y) << 8) + x0 + px_l;
            *(float4*)op       = make_float4(acc[i][0], acc[i][1], acc[i][2], acc[i][3]);
            *(float4*)(op + 4) = make_float4(acc[i][4], acc[i][5], acc[i][6], acc[i][7]);
            float s = 0.f, q = 0.f;
#pragma unroll
            for (int j = 0; j < 8; ++j) { s += acc[i][j]; q += acc[i][j] * acc[i][j]; }
            atomicAdd(&sacc[oc_l + i], s);
            atomicAdd(&qacc[oc_l + i], q);
        }
    }
    __syncthreads();
    if (tid < 64 && (ocb + tid) < Cout) {
        atomicAdd(&g_stats[ocb + tid], sacc[tid]);
        atomicAdd(&g_stats[128 + ocb + tid], qacc[tid]);
    }
}

// ---------------- BN finalize ----------------
__global__ void bnfin_kernel(const float* __restrict__ g, const float* __restrict__ b, int C) {
    int c = threadIdx.x;
    if (c < C) {
        float inv = 1.f / (float)NPIX;
        float mu  = g_stats[c] * inv;
        float var = g_stats[128 + c] * inv - mu * mu;
        float sc  = g[c] * rsqrtf(var + 1e-5f);
        g_scale[c] = sc;
        g_shift[c] = b[c] - mu * sc;
    }
}

// ---------------- final 1x1 conv (48->20) with fused bn4+relu on input --------
__global__ __launch_bounds__(256) void obj2_kernel(
    const float* __restrict__ in, const float* __restrict__ w,
    const float* __restrict__ b, float* __restrict__ out)
{
    __shared__ float wst[48 * 20];   // [ic][o]
    __shared__ float bs[20];
    int tid = threadIdx.x;
    for (int i = tid; i < 48 * 20; i += 256) {
        int o = i / 48, ic = i - o * 48;
        wst[ic * 20 + o] = w[o * 48 + ic];
    }
    if (tid < 20) bs[tid] = b[tid];
    __syncthreads();

    int p = blockIdx.x * 256 + tid;
    int n = p >> 16, pix = p & 65535;
    u64 accp[10];
#pragma unroll
    for (int o = 0; o < 10; ++o) accp[o] = pack2f(bs[2 * o], bs[2 * o + 1]);
#pragma unroll
    for (int ic = 0; ic < 48; ++ic) {
        float v = in[((size_t)(n * 48 + ic) << 16) + pix];
        v = fmaxf(v * g_scale[ic] + g_shift[ic], 0.f);
        u64 vb = bcast2(v);
#pragma unroll
        for (int o = 0; o < 10; ++o) {
            u64 wp = *(const u64*)&wst[ic * 20 + 2 * o];
            accp[o] = ffma2(wp, vb, accp[o]);
        }
    }
#pragma unroll
    for (int o = 0; o < 10; ++o) {
        float2 f = unpk(accp[o]);
        out[((size_t)(n * NOBJ + 2 * o)     << 16) + pix] = f.x;
        out[((size_t)(n * NOBJ + 2 * o + 1) << 16) + pix] = f.y;
    }
}

// ---------------- launch ----------------
extern "C" void kernel_launch(void* const* d_in, const int* in_sizes, int n_in,
                              void* d_out, int out_size)
{
    const float* feats  = (const float*)d_in[0];
    const int*   masks  = (const int*)  d_in[1];
    const float* w_ih   = (const float*)d_in[2];
    const float* w_hh   = (const float*)d_in[3];
    const float* b_ih   = (const float*)d_in[4];
    const float* b_hh   = (const float*)d_in[5];
    const float* conv1w = (const float*)d_in[6];
    const float* bn1g   = (const float*)d_in[7];
    const float* bn1b   = (const float*)d_in[8];
    const float* conv2w = (const float*)d_in[9];
    const float* bn2g   = (const float*)d_in[10];
    const float* bn2b   = (const float*)d_in[11];
    const float* conv3w = (const float*)d_in[12];
    const float* bn3g   = (const float*)d_in[13];
    const float* bn3b   = (const float*)d_in[14];
    const float* obj1w  = (const float*)d_in[15];
    const float* bn4g   = (const float*)d_in[16];
    const float* bn4b   = (const float*)d_in[17];
    const float* obj2w  = (const float*)d_in[18];
    const float* obj2b  = (const float*)d_in[19];
    float* out = (float*)d_out;

    void *pa, *pb, *pany, *pstats, *pbA, *pbB;
    cudaGetSymbolAddress(&pa, g_state_a);
    cudaGetSymbolAddress(&pb, g_state_b);
    cudaGetSymbolAddress(&pany, g_any);
    cudaGetSymbolAddress(&pstats, g_stats);
    cudaGetSymbolAddress(&pbA, g_bufA);
    cudaGetSymbolAddress(&pbB, g_bufB);
    float* sA = (float*)pa;
    float* sB = (float*)pb;
    float* bA = (float*)pbA;
    float* bB = (float*)pbB;

    cudaMemsetAsync(pany, 0, sizeof(g_any));
    any_kernel<<<2048, 256>>>(masks);
    obs_kernel<<<512, 256>>>(masks, out + (size_t)NB * NOBJ * HW);

    dim3 ggrid(1024, 4);
    gru_step<true,  false><<<ggrid, 256>>>(feats, masks, w_ih, w_hh, b_ih, b_hh, sA, sB, 0);
    gru_step<false, false><<<ggrid, 256>>>(feats, masks, w_ih, w_hh, b_ih, b_hh, sB, sA, 1);
    gru_step<false, false><<<ggrid, 256>>>(feats, masks, w_ih, w_hh, b_ih, b_hh, sA, sB, 2);
    gru_step<false, true ><<<ggrid, 256>>>(feats, masks, w_ih, w_hh, b_ih, b_hh, sB, bA, 3); // NCHW

    // conv1 7x7 128->128 (no input bn)
    cudaMemsetAsync(pstats, 0, sizeof(g_stats));
    conv_kernel<7, false><<<dim3(512, 2, 2), 256>>>(bA, conv1w, bB, 128, 128);
    bnfin_kernel<<<1, 128>>>(bn1g, bn1b, 128);

    // conv2 3x3 128->64, fused bn1+relu on input
    cudaMemsetAsync(pstats, 0, sizeof(g_stats));
    conv_kernel<3, true><<<dim3(512, 1, 2), 256>>>(bB, conv2w, bA, 128, 64);
    bnfin_kernel<<<1, 128>>>(bn2g, bn2b, 64);

    // conv3 3x3 64->48, fused bn2+relu
    cudaMemsetAsync(pstats, 0, sizeof(g_stats));
    conv_kernel<3, true><<<dim3(512, 1, 2), 256>>>(bA, conv3w, bB, 64, 48);
    bnfin_kernel<<<1, 128>>>(bn3g, bn3b, 48);

    // obj1 3x3 48->48, fused bn3+relu
    cudaMemsetAsync(pstats, 0, sizeof(g_stats));
    conv_kernel<3, true><<<dim3(512, 1, 2), 256>>>(bB, obj1w, bA, 48, 48);
    bnfin_kernel<<<1, 128>>>(bn4g, bn4b, 48);

    // obj2 1x1 48->20 + bias, fused bn4+relu
    obj2_kernel<<<512, 256>>>(bA, obj2w, obj2b, out);
}

// round 4
// speedup vs baseline: 2.3794x; 1.9939x over previous
#include <cuda_runtime.h>
#include <cuda_fp16.h>
#include <cstdint>

#define EGO   64
#define MEM   128
#define NOBJ  20
#define HW    65536     // 256*256
#define NPIX  131072    // 2 * HW
#define NB    2
#define TT    4

typedef unsigned long long u64;

// ---------------- packed f32x2 helpers ----------------
__device__ __forceinline__ u64 bcast2(float x) {
    u64 r; asm("mov.b64 %0, {%1, %1};" : "=l"(r) : "f"(x)); return r;
}
__device__ __forceinline__ u64 pack2f(float x, float y) {
    u64 r; asm("mov.b64 %0, {%1, %2};" : "=l"(r) : "f"(x), "f"(y)); return r;
}
__device__ __forceinline__ u64 ffma2(u64 a, u64 b, u64 c) {
    u64 d; asm("fma.rn.f32x2 %0, %1, %2, %3;" : "=l"(d) : "l"(a), "l"(b), "l"(c)); return d;
}
__device__ __forceinline__ float2 unpk(u64 a) {
    float2 f; asm("mov.b64 {%0, %1}, %2;" : "=f"(f.x), "=f"(f.y) : "l"(a)); return f;
}

// ---------------- smem / swizzle / mma helpers ----------------
__device__ __forceinline__ uint32_t smem_u32(const void* p) {
    uint32_t a; asm("{ .reg .u64 t; cvta.to.shared.u64 t, %1; cvt.u32.u64 %0, t; }" : "=r"(a) : "l"(p));
    return a;
}
#define SW128(o) ((o) ^ (((o) >> 3) & 0x70))

__device__ __forceinline__ void ldsm_x4(uint32_t& r0, uint32_t& r1, uint32_t& r2, uint32_t& r3,
                                        uint32_t addr) {
    asm volatile("ldmatrix.sync.aligned.m8n8.x4.shared.b16 {%0,%1,%2,%3}, [%4];"
                 : "=r"(r0), "=r"(r1), "=r"(r2), "=r"(r3) : "r"(addr));
}
__device__ __forceinline__ void mma16816(float* c, const uint32_t* a, uint32_t b0, uint32_t b1) {
    asm volatile(
        "mma.sync.aligned.m16n8k16.row.col.f32.f16.f16.f32 "
        "{%0,%1,%2,%3}, {%4,%5,%6,%7}, {%8,%9}, {%0,%1,%2,%3};"
        : "+f"(c[0]), "+f"(c[1]), "+f"(c[2]), "+f"(c[3])
        : "r"(a[0]), "r"(a[1]), "r"(a[2]), "r"(a[3]), "r"(b0), "r"(b1));
}

// ---------------- static scratch ----------------
__device__ float  g_state_a[(size_t)NPIX * MEM];
__device__ float  g_state_b[(size_t)NPIX * MEM];
__device__ float  g_bufA[(size_t)NPIX * 128];
__device__ float  g_bufB[(size_t)NPIX * 128];
__device__ __half g_h16[(size_t)NPIX * 128];
__device__ __half g_w16[49 * 128 * 128];
__device__ int    g_any[8];
__device__ float  g_stats[256];
__device__ float  g_scale[128];
__device__ float  g_shift[128];

// ---------------- any / observed ----------------
__global__ void any_kernel(const int* __restrict__ masks) {
    int idx = blockIdx.x * blockDim.x + threadIdx.x;
    int v = masks[idx];
    unsigned b = __ballot_sync(0xffffffffu, v > 0);
    if ((threadIdx.x & 31) == 0 && b)
        atomicOr(&g_any[idx >> 16], 1);
}
__global__ void obs_kernel(const int* __restrict__ masks, float* __restrict__ outobs) {
    int idx = blockIdx.x * blockDim.x + threadIdx.x;
    int n = idx >> 16, pix = idx & 65535;
    int s = 0;
#pragma unroll
    for (int t = 0; t < TT; ++t)
        s += masks[((n * TT + t) << 16) + pix] * g_any[n * TT + t];
    outobs[idx] = (float)s;
}

// ---------------- GRU step (R2, NHWC out) ----------------
template<bool FIRST>
__global__ __launch_bounds__(256) void gru_step(
    const float* __restrict__ feats, const int* __restrict__ masks,
    const float* __restrict__ w_ih, const float* __restrict__ w_hh,
    const float* __restrict__ b_ih, const float* __restrict__ b_hh,
    const float* __restrict__ hin, float* __restrict__ hout, int t)
{
    __shared__ __align__(16) float it[16 * 132];
    __shared__ __align__(16) float wt[16 * 100];

    int tid = threadIdx.x;
    int u2 = tid & 15;
    int pg = tid >> 4;
    int ub = blockIdx.y * 32;
    int p0 = blockIdx.x * 128;
    int n = p0 >> 16, pix0 = p0 & 65535;
    int px = pg * 8;

    const float* fbase = feats + ((size_t)(n * TT + t) * HW + pix0) * EGO;
    const float* hbase = hin + (size_t)p0 * MEM;

    u64 ar[2][4], az[2][4], ax[2][4], ah[2][4];
#pragma unroll
    for (int un = 0; un < 2; ++un)
#pragma unroll
        for (int j = 0; j < 4; ++j) { ar[un][j] = az[un][j] = ax[un][j] = ah[un][j] = 0ull; }

    int lp = tid >> 1;
    int kh = (tid & 1) * 8;
    const int CMAX = FIRST ? 4 : 12;

    for (int c = 0; c < CMAX; ++c) {
        int kb = c * 16;
        __syncthreads();
        {
            const float* src = (kb < 64) ? (fbase + (size_t)lp * EGO + kb + kh)
                                         : (hbase + (size_t)lp * MEM + (kb - 64) + kh);
            float4 v0 = *(const float4*)src;
            float4 v1 = *(const float4*)(src + 4);
            it[(kh + 0) * 132 + lp] = v0.x; it[(kh + 1) * 132 + lp] = v0.y;
            it[(kh + 2) * 132 + lp] = v0.z; it[(kh + 3) * 132 + lp] = v0.w;
            it[(kh + 4) * 132 + lp] = v1.x; it[(kh + 5) * 132 + lp] = v1.y;
            it[(kh + 6) * 132 + lp] = v1.z; it[(kh + 7) * 132 + lp] = v1.w;
        }
#pragma unroll
        for (int q = 0; q < 6; ++q) {
            int idx = tid + q * 256;
            int kl = idx / 96;
            int row = idx - kl * 96;
            int g = row >> 5, uu = row & 31;
            int grow = g * 128 + ub + uu;
            float val = (kb < 64) ? w_ih[grow * 64 + kb + kl]
                                  : w_hh[grow * 128 + (kb - 64) + kl];
            wt[kl * 100 + row] = val;
        }
        __syncthreads();

#pragma unroll
        for (int k = 0; k < 16; ++k) {
            const float* wrow = &wt[k * 100];
            float2 wr = *(const float2*)&wrow[0  + 2 * u2];
            float2 wz = *(const float2*)&wrow[32 + 2 * u2];
            float2 wn = *(const float2*)&wrow[64 + 2 * u2];
            u64 wrp[2] = { bcast2(wr.x), bcast2(wr.y) };
            u64 wzp[2] = { bcast2(wz.x), bcast2(wz.y) };
            u64 wnp[2] = { bcast2(wn.x), bcast2(wn.y) };
            ulonglong2 x01 = *(const ulonglong2*)&it[k * 132 + px];
            ulonglong2 x23 = *(const ulonglong2*)&it[k * 132 + px + 4];
            u64 xi[4] = { x01.x, x01.y, x23.x, x23.y };
            if (c < 4) {
#pragma unroll
                for (int un = 0; un < 2; ++un)
#pragma unroll
                    for (int j = 0; j < 4; ++j) {
                        ar[un][j] = ffma2(wrp[un], xi[j], ar[un][j]);
                        az[un][j] = ffma2(wzp[un], xi[j], az[un][j]);
                        ax[un][j] = ffma2(wnp[un], xi[j], ax[un][j]);
                    }
            } else {
#pragma unroll
                for (int un = 0; un < 2; ++un)
#pragma unroll
                    for (int j = 0; j < 4; ++j) {
                        ar[un][j] = ffma2(wrp[un], xi[j], ar[un][j]);
                        az[un][j] = ffma2(wzp[un], xi[j], az[un][j]);
                        ah[un][j] = ffma2(wnp[un], xi[j], ah[un][j]);
                    }
            }
        }
    }

    const int* mrow = masks + ((size_t)(n * TT + t) << 16) + pix0 + px;
    int mk[8];
#pragma unroll
    for (int j = 0; j < 8; ++j) mk[j] = mrow[j];

#pragma unroll
    for (int un = 0; un < 2; ++un) {
        int uc = ub + u2 * 2 + un;
        float bir = b_ih[uc], biz = b_ih[128 + uc], bin_ = b_ih[256 + uc];
        float bhr = b_hh[uc], bhz = b_hh[128 + uc], bhn = b_hh[256 + uc];
#pragma unroll
        for (int jp = 0; jp < 4; ++jp) {
            float2 fr = unpk(ar[un][jp]), fz = unpk(az[un][jp]);
            float2 fx = unpk(ax[un][jp]), fh = unpk(ah[un][jp]);
            float rr[2] = { fr.x, fr.y }, zz[2] = { fz.x, fz.y };
            float xx[2] = { fx.x, fx.y }, hp[2] = { fh.x, fh.y };
#pragma unroll
            for (int e = 0; e < 2; ++e) {
                int j = jp * 2 + e;
                float hu = FIRST ? 0.f : hin[(size_t)(p0 + px + j) * MEM + uc];
                float r = 1.f / (1.f + __expf(-(rr[e] + bir + bhr)));
                float z = 1.f / (1.f + __expf(-(zz[e] + biz + bhz)));
                float nn = tanhf(xx[e] + bin_ + r * (hp[e] + bhn));
                float hv = (1.f - z) * nn + z * hu;
                hout[(size_t)(p0 + px + j) * MEM + uc] = (mk[j] > 0) ? hv : hu;
            }
        }
    }
}

// ---------------- fp32 NHWC -> fp16 NHWC (dense, C=128) ----------------
__global__ void h16_kernel(const float* __restrict__ in, __half* __restrict__ out) {
    size_t i = ((size_t)blockIdx.x * 256 + threadIdx.x) * 8;
    float4 a = *(const float4*)(in + i);
    float4 b = *(const float4*)(in + i + 4);
    __half2 h[4] = { __floats2half2_rn(a.x, a.y), __floats2half2_rn(a.z, a.w),
                     __floats2half2_rn(b.x, b.y), __floats2half2_rn(b.z, b.w) };
    *(uint4*)(out + i) = *(const uint4*)h;
}

// ---------------- bn+relu fp32 NHWC[CIN] -> fp16 NHWC[CPAD] ----------------
template<int CIN, int CPAD>
__global__ void bnrelu_h16(const float* __restrict__ in, __half* __restrict__ out) {
    int i = blockIdx.x * 256 + threadIdx.x;     // one uint4 (8 halves)
    int px = i / (CPAD / 8);
    int c0 = (i % (CPAD / 8)) * 8;
    __half2 h[4];
#pragma unroll
    for (int j = 0; j < 4; ++j) {
        int c = c0 + 2 * j;
        float v0 = 0.f, v1 = 0.f;
        if (c < CIN) {
            float2 v = *(const float2*)(in + (size_t)px * CIN + c);
            v0 = fmaxf(v.x * g_scale[c] + g_shift[c], 0.f);
            v1 = fmaxf(v.y * g_scale[c + 1] + g_shift[c + 1], 0.f);
        }
        h[j] = __floats2half2_rn(v0, v1);
    }
    *(uint4*)(out + (size_t)px * CPAD + c0) = *(const uint4*)h;
}

// ---------------- weight prep: [oc][ic][tap] f32 -> [tap][ocpad][icpad] f16 ---
__global__ void w16prep(const float* __restrict__ w, __half* __restrict__ o,
                        int NTAP, int OCT, int ICP, int Cout, int Cin) {
    int i = blockIdx.x * 256 + threadIdx.x;
    int total = NTAP * OCT * ICP;
    if (i >= total) return;
    int tap = i / (OCT * ICP);
    int r = i - tap * (OCT * ICP);
    int oc = r / ICP, ic = r - oc * ICP;
    float v = (oc < Cout && ic < Cin) ? w[((size_t)oc * Cin + ic) * NTAP + tap] : 0.f;
    o[i] = __float2half_rn(v);
}

// ---------------- HMMA implicit-GEMM conv ----------------
// 256 thr = 8 warps (4m x 2n). CTA tile: 128 px x OCT oc. Stage k-chunk = 64 ic.
// A smem [128px][64ic] f16 SW128; B smem [OCT oc][64ic] f16 SW128. Double buffered.
// Output: fp32 NHWC [px][COUT] + BN stats.
template<int K, int ICH, int CINP, int OCT, int COUT>
__global__ __launch_bounds__(256) void conv_hmma(
    const __half* __restrict__ in, const __half* __restrict__ w16,
    float* __restrict__ out)
{
    constexpr int PAD = K / 2;
    constexpr int NS = K * K * ICH;
    constexpr int ICP = 64 * ICH;
    constexpr int ABYTES = 128 * 128;
    constexpr int BBYTES = OCT * 128;
    constexpr int NJ = OCT / 16;          // n-frags per warp (8-wide): 8 or 4
    constexpr int NI2 = NJ / 2;           // x4 B loads per kk: 4 or 2

    extern __shared__ __align__(16) char sm[];
    char* ab[2] = { sm, sm + ABYTES };
    char* bb[2] = { sm + 2 * ABYTES, sm + 2 * ABYTES + BBYTES };
    float* sacc = (float*)(sm + 2 * ABYTES + 2 * BBYTES);
    float* qacc = sacc + OCT;

    int tid = threadIdx.x;
    int lane = tid & 31, wrp = tid >> 5;
    int mw = wrp >> 1, nw = wrp & 1;
    int p0 = blockIdx.x * 128;
    int n = p0 >> 16;
    int y = (p0 >> 8) & 255;
    int x0 = p0 & 255;                    // 0 or 128

    float acc[2][NJ][4];
#pragma unroll
    for (int mi = 0; mi < 2; ++mi)
#pragma unroll
        for (int nj = 0; nj < NJ; ++nj)
#pragma unroll
            for (int e = 0; e < 4; ++e) acc[mi][nj][e] = 0.f;

    int sr = tid >> 1;        // staging row
    int hh = tid & 1;         // 32-ic half

    // ---- staging helper (all threads) ----
    auto load_stage = [&](int s, int slot) {
        int tap = s / ICH;
        int ich = s - tap * ICH;
        int ky = tap / K, kx = tap - ky * K;
        // A: 128 px rows
        {
            int gy = y + ky - PAD;
            int gx = x0 + sr + kx - PAD;
            uint4 v[4] = { {0,0,0,0}, {0,0,0,0}, {0,0,0,0}, {0,0,0,0} };
            if ((unsigned)gy < 256u && (unsigned)gx < 256u) {
                const uint4* src = (const uint4*)(in +
                    ((size_t)((n * 256 + gy) * 256 + gx)) * CINP + ich * 64 + hh * 32);
#pragma unroll
                for (int j = 0; j < 4; ++j) v[j] = src[j];
            }
            char* base = ab[slot];
#pragma unroll
            for (int j = 0; j < 4; ++j) {
                uint32_t bo = (uint32_t)sr * 128 + hh * 64 + j * 16;
                *(uint4*)(base + SW128(bo)) = v[j];
            }
        }
        // B: OCT oc rows
        if (OCT == 128 || tid < 128) {
            const uint4* src = (const uint4*)(w16 +
                ((size_t)tap * OCT + sr) * ICP + ich * 64 + hh * 32);
            char* base = bb[slot];
#pragma unroll
            for (int j = 0; j < 4; ++j) {
                uint32_t bo = (uint32_t)sr * 128 + hh * 64 + j * 16;
                *(uint4*)(base + SW128(bo)) = src[j];
            }
        }
    };

    load_stage(0, 0);
    __syncthreads();

    for (int s = 0; s < NS; ++s) {
        int slot = s & 1;
        if (s + 1 < NS) load_stage(s + 1, slot ^ 1);

        uint32_t abase = smem_u32(ab[slot]);
        uint32_t bbase = smem_u32(bb[slot]);
#pragma unroll
        for (int kk = 0; kk < 4; ++kk) {
            uint32_t afr[2][4];
#pragma unroll
            for (int mi = 0; mi < 2; ++mi) {
                uint32_t row = mw * 32 + mi * 16 + (lane & 15);
                uint32_t bo = kk * 32 + ((lane >> 4) << 4);
                ldsm_x4(afr[mi][0], afr[mi][1], afr[mi][2], afr[mi][3],
                        abase + SW128(row * 128 + bo));
            }
#pragma unroll
            for (int ni = 0; ni < NI2; ++ni) {
                uint32_t row = nw * (OCT / 2) + ni * 16 + (lane & 15);
                uint32_t bo = kk * 32 + ((lane >> 4) << 4);
                uint32_t b0, b1, b2, b3;
                ldsm_x4(b0, b1, b2, b3, bbase + SW128(row * 128 + bo));
#pragma unroll
                for (int mi = 0; mi < 2; ++mi) {
                    mma16816(acc[mi][ni * 2],     afr[mi], b0, b2);
                    mma16816(acc[mi][ni * 2 + 1], afr[mi], b1, b3);
                }
            }
        }
        __syncthreads();
    }

    // ---- epilogue: NHWC fp32 store + BN stats ----
    if (tid < OCT) { sacc[tid] = 0.f; qacc[tid] = 0.f; }
    __syncthreads();

#pragma unroll
    for (int nj = 0; nj < NJ; ++nj) {
        int col = nw * (OCT / 2) + nj * 8 + (lane & 3) * 2;
        if (col < COUT) {
            float s0 = 0.f, s1 = 0.f, q0 = 0.f, q1 = 0.f;
#pragma unroll
            for (int mi = 0; mi < 2; ++mi) {
                int row = mw * 32 + mi * 16 + (lane >> 2);
                float d0 = acc[mi][nj][0], d1 = acc[mi][nj][1];
                float d2 = acc[mi][nj][2], d3 = acc[mi][nj][3];
                *(float2*)(out + (size_t)(p0 + row) * COUT + col)     = make_float2(d0, d1);
                *(float2*)(out + (size_t)(p0 + row + 8) * COUT + col) = make_float2(d2, d3);
                s0 += d0 + d2; s1 += d1 + d3;
                q0 += d0 * d0 + d2 * d2; q1 += d1 * d1 + d3 * d3;
            }
            atomicAdd(&sacc[col], s0);     atomicAdd(&sacc[col + 1], s1);
            atomicAdd(&qacc[col], q0);     atomicAdd(&qacc[col + 1], q1);
        }
    }
    __syncthreads();
    if (tid < OCT && tid < COUT) {
        atomicAdd(&g_stats[tid], sacc[tid]);
        atomicAdd(&g_stats[128 + tid], qacc[tid]);
    }
}

// ---------------- BN finalize ----------------
__global__ void bnfin_kernel(const float* __restrict__ g, const float* __restrict__ b, int C) {
    int c = threadIdx.x;
    if (c < C) {
        float inv = 1.f / (float)NPIX;
        float mu  = g_stats[c] * inv;
        float var = g_stats[128 + c] * inv - mu * mu;
        float sc  = g[c] * rsqrtf(var + 1e-5f);
        g_scale[c] = sc;
        g_shift[c] = b[c] - mu * sc;
    }
}

// ---------------- obj2 1x1 (48->20), input fp32 NHWC[48] + fused bn4+relu -----
__global__ __launch_bounds__(256) void obj2_kernel(
    const float* __restrict__ in, const float* __restrict__ w,
    const float* __restrict__ b, float* __restrict__ out)
{
    __shared__ float wst[48 * 20];
    __shared__ float bs[20];
    int tid = threadIdx.x;
    for (int i = tid; i < 48 * 20; i += 256) {
        int o = i / 48, ic = i - o * 48;
        wst[ic * 20 + o] = w[o * 48 + ic];
    }
    if (tid < 20) bs[tid] = b[tid];
    __syncthreads();

    int p = blockIdx.x * 256 + tid;
    int n = p >> 16, pix = p & 65535;
    const float* ip = in + (size_t)p * 48;
    u64 accp[10];
#pragma unroll
    for (int o = 0; o < 10; ++o) accp[o] = pack2f(bs[2 * o], bs[2 * o + 1]);
#pragma unroll
    for (int ic = 0; ic < 48; ++ic) {
        float v = fmaxf(ip[ic] * g_scale[ic] + g_shift[ic], 0.f);
        u64 vb = bcast2(v);
#pragma unroll
        for (int o = 0; o < 10; ++o) {
            u64 wp = *(const u64*)&wst[ic * 20 + 2 * o];
            accp[o] = ffma2(wp, vb, accp[o]);
        }
    }
#pragma unroll
    for (int o = 0; o < 10; ++o) {
        float2 f = unpk(accp[o]);
        out[((size_t)(n * NOBJ + 2 * o)     << 16) + pix] = f.x;
        out[((size_t)(n * NOBJ + 2 * o + 1) << 16) + pix] = f.y;
    }
}

// ---------------- launch ----------------
extern "C" void kernel_launch(void* const* d_in, const int* in_sizes, int n_in,
                              void* d_out, int out_size)
{
    const float* feats  = (const float*)d_in[0];
    const int*   masks  = (const int*)  d_in[1];
    const float* w_ih   = (const float*)d_in[2];
    const float* w_hh   = (const float*)d_in[3];
    const float* b_ih   = (const float*)d_in[4];
    const float* b_hh   = (const float*)d_in[5];
    const float* conv1w = (const float*)d_in[6];
    const float* bn1g   = (const float*)d_in[7];
    const float* bn1b   = (const float*)d_in[8];
    const float* conv2w = (const float*)d_in[9];
    const float* bn2g   = (const float*)d_in[10];
    const float* bn2b   = (const float*)d_in[11];
    const float* conv3w = (const float*)d_in[12];
    const float* bn3g   = (const float*)d_in[13];
    const float* bn3b   = (const float*)d_in[14];
    const float* obj1w  = (const float*)d_in[15];
    const float* bn4g   = (const float*)d_in[16];
    const float* bn4b   = (const float*)d_in[17];
    const float* obj2w  = (const float*)d_in[18];
    const float* obj2b  = (const float*)d_in[19];
    float* out = (float*)d_out;

    void *pa, *pb, *pany, *pstats, *pbA, *pbB, *ph16, *pw16;
    cudaGetSymbolAddress(&pa, g_state_a);
    cudaGetSymbolAddress(&pb, g_state_b);
    cudaGetSymbolAddress(&pany, g_any);
    cudaGetSymbolAddress(&pstats, g_stats);
    cudaGetSymbolAddress(&pbA, g_bufA);
    cudaGetSymbolAddress(&pbB, g_bufB);
    cudaGetSymbolAddress(&ph16, g_h16);
    cudaGetSymbolAddress(&pw16, g_w16);
    float* sA = (float*)pa;
    float* sB = (float*)pb;
    float* bA = (float*)pbA;
    float* bB = (float*)pbB;
    __half* h16 = (__half*)ph16;
    __half* w16 = (__half*)pw16;

    // smem opt-in for conv kernels
    auto* c1 = conv_hmma<7, 2, 128, 128, 128>;
    auto* c2 = conv_hmma<3, 2, 128, 64, 64>;
    auto* c3 = conv_hmma<3, 1, 64, 64, 48>;
    auto* c4 = conv_hmma<3, 1, 64, 64, 48>;
    const int SM1 = 2 * 16384 + 2 * 16384 + 128 * 8;     // 66560
    const int SM2 = 2 * 16384 + 2 * 8192 + 64 * 8;       // 49664
    cudaFuncSetAttribute(c1, cudaFuncAttributeMaxDynamicSharedMemorySize, SM1);
    cudaFuncSetAttribute(c2, cudaFuncAttributeMaxDynamicSharedMemorySize, SM2);
    cudaFuncSetAttribute(c3, cudaFuncAttributeMaxDynamicSharedMemorySize, SM2);

    cudaMemsetAsync(pany, 0, sizeof(g_any));
    any_kernel<<<2048, 256>>>(masks);
    obs_kernel<<<512, 256>>>(masks, out + (size_t)NB * NOBJ * HW);

    // conv1 weights early (independent)
    w16prep<<<3136, 256>>>(conv1w, w16, 49, 128, 128, 128, 128);

    dim3 ggrid(1024, 4);
    gru_step<true ><<<ggrid, 256>>>(feats, masks, w_ih, w_hh, b_ih, b_hh, sA, sB, 0);
    gru_step<false><<<ggrid, 256>>>(feats, masks, w_ih, w_hh, b_ih, b_hh, sB, sA, 1);
    gru_step<false><<<ggrid, 256>>>(feats, masks, w_ih, w_hh, b_ih, b_hh, sA, sB, 2);
    gru_step<false><<<ggrid, 256>>>(feats, masks, w_ih, w_hh, b_ih, b_hh, sB, sA, 3);

    // state fp32 NHWC -> fp16 NHWC
    h16_kernel<<<8192, 256>>>(sA, h16);

    // conv1 7x7 128->128 : out fp32 NHWC[128] in bufB
    cudaMemsetAsync(pstats, 0, sizeof(g_stats));
    c1<<<1024, 256, SM1>>>(h16, w16, bB);
    bnfin_kernel<<<1, 128>>>(bn1g, bn1b, 128);
    bnrelu_h16<128, 128><<<NPIX * 128 / 8 / 256, 256>>>(bB, h16);

    // conv2 3x3 128->64 : out NHWC[64] in bufA
    w16prep<<<(9 * 64 * 128 + 255) / 256, 256>>>(conv2w, w16, 9, 64, 128, 64, 128);
    cudaMemsetAsync(pstats, 0, sizeof(g_stats));
    c2<<<1024, 256, SM2>>>(h16, w16, bA);
    bnfin_kernel<<<1, 128>>>(bn2g, bn2b, 64);
    bnrelu_h16<64, 64><<<NPIX * 64 / 8 / 256, 256>>>(bA, h16);

    // conv3 3x3 64->48 : out NHWC[48] in bufB
    w16prep<<<(9 * 64 * 64 + 255) / 256, 256>>>(conv3w, w16, 9, 64, 64, 48, 64);
    cudaMemsetAsync(pstats, 0, sizeof(g_stats));
    c3<<<1024, 256, SM2>>>(h16, w16, bB);
    bnfin_kernel<<<1, 128>>>(bn3g, bn3b, 48);
    bnrelu_h16<48, 64><<<NPIX * 64 / 8 / 256, 256>>>(bB, h16);

    // obj1 3x3 48->48 : out NHWC[48] in bufA
    w16prep<<<(9 * 64 * 64 + 255) / 256, 256>>>(obj1w, w16, 9, 64, 64, 48, 48);
    cudaMemsetAsync(pstats, 0, sizeof(g_stats));
    c4<<<1024, 256, SM2>>>(h16, w16, bA);
    bnfin_kernel<<<1, 128>>>(bn4g, bn4b, 48);

    // obj2 1x1 48->20 + bias (fused bn4+relu)
    obj2_kernel<<<512, 256>>>(bA, obj2w, obj2b, out);
}

// round 5
// speedup vs baseline: 3.3891x; 1.4243x over previous
#include <cuda_runtime.h>
#include <cuda_fp16.h>
#include <cstdint>

#define EGO   64
#define MEM   128
#define NOBJ  20
#define HW    65536     // 256*256
#define NPIX  131072    // 2 * HW
#define NB    2
#define TT    4

typedef unsigned long long u64;

// ---------------- packed f32x2 helpers ----------------
__device__ __forceinline__ u64 bcast2(float x) {
    u64 r; asm("mov.b64 %0, {%1, %1};" : "=l"(r) : "f"(x)); return r;
}
__device__ __forceinline__ u64 pack2f(float x, float y) {
    u64 r; asm("mov.b64 %0, {%1, %2};" : "=l"(r) : "f"(x), "f"(y)); return r;
}
__device__ __forceinline__ u64 ffma2(u64 a, u64 b, u64 c) {
    u64 d; asm("fma.rn.f32x2 %0, %1, %2, %3;" : "=l"(d) : "l"(a), "l"(b), "l"(c)); return d;
}
__device__ __forceinline__ float2 unpk(u64 a) {
    float2 f; asm("mov.b64 {%0, %1}, %2;" : "=f"(f.x), "=f"(f.y) : "l"(a)); return f;
}

// ---------------- fast transcendentals (MUFU, high accuracy forms) -----------
__device__ __forceinline__ float fast_sigmoid(float x) {
    float e; asm("ex2.approx.f32 %0, %1;" : "=f"(e) : "f"(-1.4426950408889634f * x));
    float r; asm("rcp.approx.f32 %0, %1;" : "=f"(r) : "f"(1.f + e));
    return r;
}
__device__ __forceinline__ float fast_tanh(float x) {
    float e; asm("ex2.approx.f32 %0, %1;" : "=f"(e) : "f"(2.8853900817779268f * x));
    float r; asm("rcp.approx.f32 %0, %1;" : "=f"(r) : "f"(1.f + e));
    return 1.f - 2.f * r;
}

// ---------------- smem / swizzle / mma helpers ----------------
__device__ __forceinline__ uint32_t smem_u32(const void* p) {
    uint32_t a; asm("{ .reg .u64 t; cvta.to.shared.u64 t, %1; cvt.u32.u64 %0, t; }" : "=r"(a) : "l"(p));
    return a;
}
#define SW128(o) ((o) ^ (((o) >> 3) & 0x70))

__device__ __forceinline__ void ldsm_x4(uint32_t& r0, uint32_t& r1, uint32_t& r2, uint32_t& r3,
                                        uint32_t addr) {
    asm volatile("ldmatrix.sync.aligned.m8n8.x4.shared.b16 {%0,%1,%2,%3}, [%4];"
                 : "=r"(r0), "=r"(r1), "=r"(r2), "=r"(r3) : "r"(addr));
}
__device__ __forceinline__ void mma16816(float* c, const uint32_t* a, uint32_t b0, uint32_t b1) {
    asm volatile(
        "mma.sync.aligned.m16n8k16.row.col.f32.f16.f16.f32 "
        "{%0,%1,%2,%3}, {%4,%5,%6,%7}, {%8,%9}, {%0,%1,%2,%3};"
        : "+f"(c[0]), "+f"(c[1]), "+f"(c[2]), "+f"(c[3])
        : "r"(a[0]), "r"(a[1]), "r"(a[2]), "r"(a[3]), "r"(b0), "r"(b1));
}

// ---------------- static scratch ----------------
__device__ __half g_hA[(size_t)NPIX * 128];      // GRU state ping
__device__ __half g_hB[(size_t)NPIX * 128];      // GRU state pong (final -> conv1 input)
__device__ __half g_act16[(size_t)NPIX * 256];   // decoder hi/lo activations
__device__ float  g_bufA[(size_t)NPIX * 128];
__device__ float  g_bufB[(size_t)NPIX * 128];
__device__ __half g_w16[49 * 128 * 128];         // conv weights (reused per layer)
__device__ __half g_w16g[4 * 3 * 128 * 64];      // GRU weights
__device__ int    g_any[8];
__device__ float  g_stats[256];
__device__ float  g_scale[128];
__device__ float  g_shift[128];

// ---------------- any / observed ----------------
__global__ void any_kernel(const int* __restrict__ masks) {
    int idx = blockIdx.x * blockDim.x + threadIdx.x;
    int v = masks[idx];
    unsigned b = __ballot_sync(0xffffffffu, v > 0);
    if ((threadIdx.x & 31) == 0 && b)
        atomicOr(&g_any[idx >> 16], 1);
}
__global__ void obs_kernel(const int* __restrict__ masks, float* __restrict__ outobs) {
    int idx = blockIdx.x * blockDim.x + threadIdx.x;
    int n = idx >> 16, pix = idx & 65535;
    int s = 0;
#pragma unroll
    for (int t = 0; t < TT; ++t)
        s += masks[((n * TT + t) << 16) + pix] * g_any[n * TT + t];
    outobs[idx] = (float)s;
}

// ---------------- GRU weight prep ----------------
// layout: [bb 4][chunk 3][row 128][k 64] fp16; row = 4*ul + gate(r,z,nx,nh)
__global__ void w16gru_prep(const float* __restrict__ wih, const float* __restrict__ whh,
                            __half* __restrict__ o) {
    int i = blockIdx.x * 256 + threadIdx.x;
    if (i >= 4 * 3 * 128 * 64) return;
    int bb = i / 24576; int r = i - bb * 24576;
    int c  = r / 8192;  int r2 = r - c * 8192;
    int row = r2 >> 6;  int kk = r2 & 63;
    int ul = row >> 2, g4 = row & 3;
    int gu = bb * 32 + ul;
    float v = 0.f;
    if (g4 == 0)      v = (c == 0) ? wih[(      gu) * 64 + kk] : whh[(      gu) * 128 + (c - 1) * 64 + kk];
    else if (g4 == 1) v = (c == 0) ? wih[(128 + gu) * 64 + kk] : whh[(128 + gu) * 128 + (c - 1) * 64 + kk];
    else if (g4 == 2) v = (c == 0) ? wih[(256 + gu) * 64 + kk] : 0.f;
    else              v = (c == 0) ? 0.f : whh[(256 + gu) * 128 + (c - 1) * 64 + kk];
    o[i] = __float2half_rn(v);
}

// ---------------- GRU step via HMMA ----------------
// grid (1024 px-tiles, 4 unit-blocks), 256 thr. C[128px x 128cols], K=192 (3x64).
// smem: A db 2x16KB @0, B 3x16KB @32768; epilogue gbuf f32 128x132 @0 (reuse);
// tail @81920: sbias 192f, wcnt 4i, cnts 1i (pad), clist 128i, ulist 128i
#define GRU_SMEM (81920 + 768 + 32 + 512 + 512)

template<bool FIRST>
__global__ __launch_bounds__(256, 2) void gru_hmma(
    const float* __restrict__ feats, const int* __restrict__ masks,
    const __half* __restrict__ w16g,
    const float* __restrict__ b_ih, const float* __restrict__ b_hh,
    const __half* __restrict__ hin, __half* __restrict__ hout, int t)
{
    extern __shared__ char sm[];
    float* gbuf = (float*)sm;
    float* sbias = (float*)(sm + 81920);
    int* wcnt  = (int*)(sm + 81920 + 768);
    int* cnts  = (int*)(sm + 81920 + 768 + 16);
    int* clist = (int*)(sm + 81920 + 768 + 32);
    int* ulist = (int*)(sm + 81920 + 768 + 32 + 512);

    int tid = threadIdx.x;
    int lane = tid & 31, wrp = tid >> 5;
    int mw = wrp >> 1, nw = wrp & 1;
    int p0 = blockIdx.x * 128;
    int bb = blockIdx.y;
    int ub = bb * 32;
    int n = p0 >> 16, pix0 = p0 & 65535;

    const int* mrow = masks + ((size_t)(n * TT + t) << 16) + pix0;

    // ---- mask compaction + bias preload ----
    int mv = 0; unsigned bal = 0; int posm = 0;
    if (tid < 128) {
        mv = mrow[tid] > 0;
        bal = __ballot_sync(0xffffffffu, mv);
        posm = __popc(bal & ((1u << lane) - 1));
        if (lane == 0) wcnt[tid >> 5] = __popc(bal);
    }
    if (tid < 96) {
        int g = tid >> 5, u = tid & 31;
        sbias[tid] = b_ih[g * 128 + ub + u];
    } else if (tid < 192) {
        int t2 = tid - 96;
        int g = t2 >> 5, u = t2 & 31;
        sbias[tid] = b_hh[g * 128 + ub + u];
    }
    __syncthreads();
    if (tid < 128) {
        int w = tid >> 5;
        int off = 0;
#pragma unroll
        for (int j = 0; j < 4; ++j) if (j < w) off += wcnt[j];
        if (mv) clist[off + posm] = tid;
        else    ulist[32 * w - off + lane - posm] = tid;
        if (tid == 0) cnts[0] = wcnt[0] + wcnt[1] + wcnt[2] + wcnt[3];
    }

    const int CH = FIRST ? 1 : 3;
    int px = tid >> 1, sg = tid & 1;

    // ---- stage B (all chunks, once) ----
    {
        int sr = tid >> 1, h2 = tid & 1;
        for (int c = 0; c < CH; ++c) {
            const __half* src = w16g + ((size_t)((bb * 3 + c) * 128 + sr)) * 64 + h2 * 32;
            char* base = sm + 32768 + c * 16384;
#pragma unroll
            for (int j = 0; j < 4; ++j) {
                uint4 v = *(const uint4*)(src + j * 8);
                uint32_t bo = (uint32_t)sr * 128 + h2 * 64 + j * 16;
                *(uint4*)(base + SW128(bo)) = v;
            }
        }
    }

    // ---- stage A helper ----
    auto stageA = [&](int c, int slot) {
        char* base = sm + slot * 16384;
        if (c == 0) {
            const float* src = feats + ((size_t)(n * TT + t) * HW + pix0 + px) * 64 + sg * 32;
#pragma unroll
            for (int j = 0; j < 4; ++j) {
                float4 a = *(const float4*)(src + j * 8);
                float4 b = *(const float4*)(src + j * 8 + 4);
                __half2 h[4] = { __floats2half2_rn(a.x, a.y), __floats2half2_rn(a.z, a.w),
                                 __floats2half2_rn(b.x, b.y), __floats2half2_rn(b.z, b.w) };
                uint32_t bo = (uint32_t)px * 128 + sg * 64 + j * 16;
                *(uint4*)(base + SW128(bo)) = *(const uint4*)h;
            }
        } else {
            const __half* src = hin + ((size_t)(p0 + px)) * 128 + (c - 1) * 64 + sg * 32;
#pragma unroll
            for (int j = 0; j < 4; ++j) {
                uint4 v = *(const uint4*)(src + j * 8);
                uint32_t bo = (uint32_t)px * 128 + sg * 64 + j * 16;
                *(uint4*)(base + SW128(bo)) = v;
            }
        }
    };

    float acc[2][8][4];
#pragma unroll
    for (int mi = 0; mi < 2; ++mi)
#pragma unroll
        for (int nj = 0; nj < 8; ++nj)
#pragma unroll
            for (int e = 0; e < 4; ++e) acc[mi][nj][e] = 0.f;

    stageA(0, 0);
    __syncthreads();

    for (int c = 0; c < CH; ++c) {
        int slot = c & 1;
        if (c + 1 < CH) stageA(c + 1, slot ^ 1);

        uint32_t abase = smem_u32(sm + slot * 16384);
        uint32_t bbase = smem_u32(sm + 32768 + c * 16384);
#pragma unroll
        for (int kk = 0; kk < 4; ++kk) {
            uint32_t bo = kk * 32 + ((lane >> 4) << 4);
            uint32_t afr[2][4];
#pragma unroll
            for (int mi = 0; mi < 2; ++mi) {
                uint32_t row = mw * 32 + mi * 16 + (lane & 15);
                ldsm_x4(afr[mi][0], afr[mi][1], afr[mi][2], afr[mi][3],
                        abase + SW128(row * 128 + bo));
            }
#pragma unroll
            for (int ni = 0; ni < 4; ++ni) {
                uint32_t row = nw * 64 + ni * 16 + (lane & 15);
                uint32_t b0, b1, b2, b3;
                ldsm_x4(b0, b1, b2, b3, bbase + SW128(row * 128 + bo));
#pragma unroll
                for (int mi = 0; mi < 2; ++mi) {
                    mma16816(acc[mi][ni * 2],     afr[mi], b0, b2);
                    mma16816(acc[mi][ni * 2 + 1], afr[mi], b1, b3);
                }
            }
        }
        __syncthreads();
    }

    // ---- transpose accums to smem gbuf [px][132] ----
#pragma unroll
    for (int mi = 0; mi < 2; ++mi)
#pragma unroll
        for (int nj = 0; nj < 8; ++nj) {
            int row = mw * 32 + mi * 16 + (lane >> 2);
            int col = nw * 64 + nj * 8 + (lane & 3) * 2;
            *(float2*)&gbuf[row * 132 + col]       = make_float2(acc[mi][nj][0], acc[mi][nj][1]);
            *(float2*)&gbuf[(row + 8) * 132 + col] = make_float2(acc[mi][nj][2], acc[mi][nj][3]);
        }
    __syncthreads();

    // ---- epilogue: masked px compute, unmasked px copy ----
    int cnt = cnts[0];
    for (int i = tid; i < 2 * cnt; i += 256) {
        int pxl = clist[i >> 1];
        int half = i & 1;
        __half hold[16];
        if (!FIRST) {
            const __half* hp = hin + ((size_t)(p0 + pxl)) * 128 + ub + half * 16;
            *(uint4*)&hold[0] = *(const uint4*)hp;
            *(uint4*)&hold[8] = *(const uint4*)(hp + 8);
        }
        __half hnew[16];
#pragma unroll
        for (int u = 0; u < 16; ++u) {
            int ul = half * 16 + u;
            float4 g = *(float4*)&gbuf[pxl * 132 + ul * 4];
            float r = fast_sigmoid(g.x + sbias[ul] + sbias[96 + ul]);
            float z = fast_sigmoid(g.y + sbias[32 + ul] + sbias[128 + ul]);
            float nv = fast_tanh(g.z + sbias[64 + ul] + r * (g.w + sbias[160 + ul]));
            float ho = FIRST ? 0.f : __half2float(hold[u]);
            float hv = nv + z * (ho - nv);
            hnew[u] = __float2half_rn(hv);
        }
        __half* op = hout + ((size_t)(p0 + pxl)) * 128 + ub + half * 16;
        *(uint4*)op       = *(const uint4*)&hnew[0];
        *(uint4*)(op + 8) = *(const uint4*)&hnew[8];
    }
    int un = 128 - cnt;
    for (int i = tid; i < 2 * un; i += 256) {
        int pxl = ulist[i >> 1];
        int half = i & 1;
        __half* op = hout + ((size_t)(p0 + pxl)) * 128 + ub + half * 16;
        if (FIRST) {
            uint4 z = make_uint4(0, 0, 0, 0);
            *(uint4*)op = z; *(uint4*)(op + 8) = z;
        } else {
            const __half* hp = hin + ((size_t)(p0 + pxl)) * 128 + ub + half * 16;
            *(uint4*)op       = *(const uint4*)hp;
            *(uint4*)(op + 8) = *(const uint4*)(hp + 8);
        }
    }
}

// ---------------- bn+relu f32 -> hi/lo fp16 NHWC [hi CHI][lo CHI] -------------
template<int CIN, int CHI>
__global__ void bnrelu_hl(const float* __restrict__ in, __half* __restrict__ out) {
    int i = blockIdx.x * 256 + threadIdx.x;
    int px = i / (CHI / 8);
    int c0 = (i % (CHI / 8)) * 8;
    __half2 hi[4], lo[4];
#pragma unroll
    for (int j = 0; j < 4; ++j) {
        int c = c0 + 2 * j;
        float v0 = 0.f, v1 = 0.f;
        if (c < CIN) {
            float2 v = *(const float2*)(in + (size_t)px * CIN + c);
            v0 = fmaxf(v.x * g_scale[c] + g_shift[c], 0.f);
            v1 = fmaxf(v.y * g_scale[c + 1] + g_shift[c + 1], 0.f);
        }
        __half h0 = __float2half_rn(v0), h1 = __float2half_rn(v1);
        hi[j] = __halves2half2(h0, h1);
        lo[j] = __floats2half2_rn(v0 - __half2float(h0), v1 - __half2float(h1));
    }
    *(uint4*)(out + (size_t)px * (2 * CHI) + c0)       = *(const uint4*)hi;
    *(uint4*)(out + (size_t)px * (2 * CHI) + CHI + c0) = *(const uint4*)lo;
}

// ---------------- weight prep ----------------
__global__ void w16prep(const float* __restrict__ w, __half* __restrict__ o,
                        int NTAP, int OCT, int ICP, int Cout, int Cin) {
    int i = blockIdx.x * 256 + threadIdx.x;
    if (i >= NTAP * OCT * ICP) return;
    int tap = i / (OCT * ICP);
    int r = i - tap * (OCT * ICP);
    int oc = r / ICP, ic = r - oc * ICP;
    float v = (oc < Cout && ic < Cin) ? w[((size_t)oc * Cin + ic) * NTAP + tap] : 0.f;
    o[i] = __float2half_rn(v);
}
__global__ void w16prep_hl(const float* __restrict__ w, __half* __restrict__ o,
                           int NTAP, int OCT, int ICP, int Cout, int Cin) {
    int i = blockIdx.x * 256 + threadIdx.x;
    if (i >= NTAP * OCT * ICP) return;
    int tap = i / (OCT * ICP);
    int r = i - tap * (OCT * ICP);
    int oc = r / ICP, ic = r - oc * ICP;
    float v = (oc < Cout && ic < Cin) ? w[((size_t)oc * Cin + ic) * NTAP + tap] : 0.f;
    __half h = __float2half_rn(v);
    size_t base = ((size_t)tap * OCT + oc) * (2 * ICP);
    o[base + ic] = h;
    o[base + ICP + ic] = __float2half_rn(v - __half2float(h));
}

// ---------------- HMMA implicit-GEMM conv (optional hi/lo 3-pass) ------------
template<int K, int ICH, int CINP, int OCT, int COUT, int PHASES>
__global__ __launch_bounds__(256) void conv_hmma(
    const __half* __restrict__ in, const __half* __restrict__ w16,
    float* __restrict__ out)
{
    constexpr int PAD = K / 2;
    constexpr int NS = K * K * PHASES * ICH;
    constexpr int BW = (PHASES == 3 ? 2 : 1) * ICH * 64;   // weight row width
    constexpr int ABYTES = 128 * 128;
    constexpr int BBYTES = OCT * 128;
    constexpr int NJ = OCT / 16;
    constexpr int NI2 = NJ / 2;

    extern __shared__ __align__(16) char sm[];
    char* ab[2] = { sm, sm + ABYTES };
    char* bb[2] = { sm + 2 * ABYTES, sm + 2 * ABYTES + BBYTES };
    float* sacc = (float*)(sm + 2 * ABYTES + 2 * BBYTES);
    float* qacc = sacc + OCT;

    int tid = threadIdx.x;
    int lane = tid & 31, wrp = tid >> 5;
    int mw = wrp >> 1, nw = wrp & 1;
    int p0 = blockIdx.x * 128;
    int n = p0 >> 16;
    int y = (p0 >> 8) & 255;
    int x0 = p0 & 255;

    float acc[2][NJ][4];
#pragma unroll
    for (int mi = 0; mi < 2; ++mi)
#pragma unroll
        for (int nj = 0; nj < NJ; ++nj)
#pragma unroll
            for (int e = 0; e < 4; ++e) acc[mi][nj][e] = 0.f;

    int sr = tid >> 1;
    int hh = tid & 1;

    auto load_stage = [&](int s, int slot) {
        int tap = s / (PHASES * ICH);
        int rem = s - tap * (PHASES * ICH);
        int p = rem / ICH, i = rem - p * ICH;
        int aoff = (p == 2) ? ICH + i : i;
        int boff = (p == 1) ? ICH + i : i;
        int ky = tap / K, kx = tap - ky * K;
        {
            int gy = y + ky - PAD;
            int gx = x0 + sr + kx - PAD;
            uint4 v[4] = { {0,0,0,0}, {0,0,0,0}, {0,0,0,0}, {0,0,0,0} };
            if ((unsigned)gy < 256u && (unsigned)gx < 256u) {
                const uint4* src = (const uint4*)(in +
                    ((size_t)((n * 256 + gy) * 256 + gx)) * CINP + aoff * 64 + hh * 32);
#pragma unroll
                for (int j = 0; j < 4; ++j) v[j] = src[j];
            }
            char* base = ab[slot];
#pragma unroll
            for (int j = 0; j < 4; ++j) {
                uint32_t bo = (uint32_t)sr * 128 + hh * 64 + j * 16;
                *(uint4*)(base + SW128(bo)) = v[j];
            }
        }
        if (OCT == 128 || tid < 128) {
            const uint4* src = (const uint4*)(w16 +
                ((size_t)tap * OCT + sr) * BW + boff * 64 + hh * 32);
            char* base = bb[slot];
#pragma unroll
            for (int j = 0; j < 4; ++j) {
                uint32_t bo = (uint32_t)sr * 128 + hh * 64 + j * 16;
                *(uint4*)(base + SW128(bo)) = src[j];
            }
        }
    };

    load_stage(0, 0);
    __syncthreads();

    for (int s = 0; s < NS; ++s) {
        int slot = s & 1;
        if (s + 1 < NS) load_stage(s + 1, slot ^ 1);

        uint32_t abase = smem_u32(ab[slot]);
        uint32_t bbase = smem_u32(bb[slot]);
#pragma unroll
        for (int kk = 0; kk < 4; ++kk) {
            uint32_t afr[2][4];
#pragma unroll
            for (int mi = 0; mi < 2; ++mi) {
                uint32_t row = mw * 32 + mi * 16 + (lane & 15);
                uint32_t bo = kk * 32 + ((lane >> 4) << 4);
                ldsm_x4(afr[mi][0], afr[mi][1], afr[mi][2], afr[mi][3],
                        abase + SW128(row * 128 + bo));
            }
#pragma unroll
            for (int ni = 0; ni < NI2; ++ni) {
                uint32_t row = nw * (OCT / 2) + ni * 16 + (lane & 15);
                uint32_t bo = kk * 32 + ((lane >> 4) << 4);
                uint32_t b0, b1, b2, b3;
                ldsm_x4(b0, b1, b2, b3, bbase + SW128(row * 128 + bo));
#pragma unroll
                for (int mi = 0; mi < 2; ++mi) {
                    mma16816(acc[mi][ni * 2],     afr[mi], b0, b2);
                    mma16816(acc[mi][ni * 2 + 1], afr[mi], b1, b3);
                }
            }
        }
        __syncthreads();
    }

    if (tid < OCT) { sacc[tid] = 0.f; qacc[tid] = 0.f; }
    __syncthreads();

#pragma unroll
    for (int nj = 0; nj < NJ; ++nj) {
        int col = nw * (OCT / 2) + nj * 8 + (lane & 3) * 2;
        if (col < COUT) {
            float s0 = 0.f, s1 = 0.f, q0 = 0.f, q1 = 0.f;
#pragma unroll
            for (int mi = 0; mi < 2; ++mi) {
                int row = mw * 32 + mi * 16 + (lane >> 2);
                float d0 = acc[mi][nj][0], d1 = acc[mi][nj][1];
                float d2 = acc[mi][nj][2], d3 = acc[mi][nj][3];
                *(float2*)(out + (size_t)(p0 + row) * COUT + col)     = make_float2(d0, d1);
                *(float2*)(out + (size_t)(p0 + row + 8) * COUT + col) = make_float2(d2, d3);
                s0 += d0 + d2; s1 += d1 + d3;
                q0 += d0 * d0 + d2 * d2; q1 += d1 * d1 + d3 * d3;
            }
            atomicAdd(&sacc[col], s0);     atomicAdd(&sacc[col + 1], s1);
            atomicAdd(&qacc[col], q0);     atomicAdd(&qacc[col + 1], q1);
        }
    }
    __syncthreads();
    if (tid < OCT && tid < COUT) {
        atomicAdd(&g_stats[tid], sacc[tid]);
        atomicAdd(&g_stats[128 + tid], qacc[tid]);
    }
}

// ---------------- BN finalize ----------------
__global__ void bnfin_kernel(const float* __restrict__ g, const float* __restrict__ b, int C) {
    int c = threadIdx.x;
    if (c < C) {
        float inv = 1.f / (float)NPIX;
        float mu  = g_stats[c] * inv;
        float var = g_stats[128 + c] * inv - mu * mu;
        float sc  = g[c] * rsqrtf(var + 1e-5f);
        g_scale[c] = sc;
        g_shift[c] = b[c] - mu * sc;
    }
}

// ---------------- obj2 1x1 (48->20), fp32 NHWC[48] + fused bn4+relu ----------
__global__ __launch_bounds__(256) void obj2_kernel(
    const float* __restrict__ in, const float* __restrict__ w,
    const float* __restrict__ b, float* __restrict__ out)
{
    __shared__ float wst[48 * 20];
    __shared__ float bs[20];
    int tid = threadIdx.x;
    for (int i = tid; i < 48 * 20; i += 256) {
        int o = i / 48, ic = i - o * 48;
        wst[ic * 20 + o] = w[o * 48 + ic];
    }
    if (tid < 20) bs[tid] = b[tid];
    __syncthreads();

    int p = blockIdx.x * 256 + tid;
    int n = p >> 16, pix = p & 65535;
    const float* ip = in + (size_t)p * 48;
    u64 accp[10];
#pragma unroll
    for (int o = 0; o < 10; ++o) accp[o] = pack2f(bs[2 * o], bs[2 * o + 1]);
#pragma unroll
    for (int ic = 0; ic < 48; ++ic) {
        float v = fmaxf(ip[ic] * g_scale[ic] + g_shift[ic], 0.f);
        u64 vb = bcast2(v);
#pragma unroll
        for (int o = 0; o < 10; ++o) {
            u64 wp = *(const u64*)&wst[ic * 20 + 2 * o];
            accp[o] = ffma2(wp, vb, accp[o]);
        }
    }
#pragma unroll
    for (int o = 0; o < 10; ++o) {
        float2 f = unpk(accp[o]);
        out[((size_t)(n * NOBJ + 2 * o)     << 16) + pix] = f.x;
        out[((size_t)(n * NOBJ + 2 * o + 1) << 16) + pix] = f.y;
    }
}

// ---------------- launch ----------------
extern "C" void kernel_launch(void* const* d_in, const int* in_sizes, int n_in,
                              void* d_out, int out_size)
{
    const float* feats  = (const float*)d_in[0];
    const int*   masks  = (const int*)  d_in[1];
    const float* w_ih   = (const float*)d_in[2];
    const float* w_hh   = (const float*)d_in[3];
    const float* b_ih   = (const float*)d_in[4];
    const float* b_hh   = (const float*)d_in[5];
    const float* conv1w = (const float*)d_in[6];
    const float* bn1g   = (const float*)d_in[7];
    const float* bn1b   = (const float*)d_in[8];
    const float* conv2w = (const float*)d_in[9];
    const float* bn2g   = (const float*)d_in[10];
    const float* bn2b   = (const float*)d_in[11];
    const float* conv3w = (const float*)d_in[12];
    const float* bn3g   = (const float*)d_in[13];
    const float* bn3b   = (const float*)d_in[14];
    const float* obj1w  = (const float*)d_in[15];
    const float* bn4g   = (const float*)d_in[16];
    const float* bn4b   = (const float*)d_in[17];
    const float* obj2w  = (const float*)d_in[18];
    const float* obj2b  = (const float*)d_in[19];
    float* out = (float*)d_out;

    void *pany, *pstats, *pbA, *pbB, *phA, *phB, *pact, *pw16, *pw16g;
    cudaGetSymbolAddress(&pany, g_any);
    cudaGetSymbolAddress(&pstats, g_stats);
    cudaGetSymbolAddress(&pbA, g_bufA);
    cudaGetSymbolAddress(&pbB, g_bufB);
    cudaGetSymbolAddress(&phA, g_hA);
    cudaGetSymbolAddress(&phB, g_hB);
    cudaGetSymbolAddress(&pact, g_act16);
    cudaGetSymbolAddress(&pw16, g_w16);
    cudaGetSymbolAddress(&pw16g, g_w16g);
    float* bA = (float*)pbA;
    float* bB = (float*)pbB;
    __half* hA = (__half*)phA;
    __half* hB = (__half*)phB;
    __half* act = (__half*)pact;
    __half* w16 = (__half*)pw16;
    __half* w16g = (__half*)pw16g;

    auto* g0 = gru_hmma<true>;
    auto* g1 = gru_hmma<false>;
    auto* c1 = conv_hmma<7, 2, 128, 128, 128, 1>;
    auto* c2 = conv_hmma<3, 2, 256, 64, 64, 3>;
    auto* c3 = conv_hmma<3, 1, 128, 64, 48, 3>;
    const int SM1 = 2 * 16384 + 2 * 16384 + 128 * 8;
    const int SM2 = 2 * 16384 + 2 * 8192 + 64 * 8;
    cudaFuncSetAttribute(g0, cudaFuncAttributeMaxDynamicSharedMemorySize, GRU_SMEM);
    cudaFuncSetAttribute(g1, cudaFuncAttributeMaxDynamicSharedMemorySize, GRU_SMEM);
    cudaFuncSetAttribute(c1, cudaFuncAttributeMaxDynamicSharedMemorySize, SM1);
    cudaFuncSetAttribute(c2, cudaFuncAttributeMaxDynamicSharedMemorySize, SM2);
    cudaFuncSetAttribute(c3, cudaFuncAttributeMaxDynamicSharedMemorySize, SM2);

    cudaMemsetAsync(pany, 0, sizeof(g_any));
    any_kernel<<<2048, 256>>>(masks);
    obs_kernel<<<512, 256>>>(masks, out + (size_t)NB * NOBJ * HW);

    // weight preps that are independent of the pipeline
    w16gru_prep<<<384, 256>>>(w_ih, w_hh, w16g);
    w16prep<<<3136, 256>>>(conv1w, w16, 49, 128, 128, 128, 128);   // conv1

    dim3 ggrid(1024, 4);
    g0<<<ggrid, 256, GRU_SMEM>>>(feats, masks, w16g, b_ih, b_hh, hA, hA, 0);
    g1<<<ggrid, 256, GRU_SMEM>>>(feats, masks, w16g, b_ih, b_hh, hA, hB, 1);
    g1<<<ggrid, 256, GRU_SMEM>>>(feats, masks, w16g, b_ih, b_hh, hB, hA, 2);
    g1<<<ggrid, 256, GRU_SMEM>>>(feats, masks, w16g, b_ih, b_hh, hA, hB, 3);  // final -> hB

    // conv1 7x7 128->128 (fp16 single-pass) -> fp32 NHWC[128] in bufB
    cudaMemsetAsync(pstats, 0, sizeof(g_stats));
    c1<<<1024, 256, SM1>>>(hB, w16, bB);
    bnfin_kernel<<<1, 128>>>(bn1g, bn1b, 128);

    // conv2 3x3 128->64 (hi/lo 3-pass)
    bnrelu_hl<128, 128><<<8192, 256>>>(bB, act);
    w16prep_hl<<<288, 256>>>(conv2w, w16, 9, 64, 128, 64, 128);
    cudaMemsetAsync(pstats, 0, sizeof(g_stats));
    c2<<<1024, 256, SM2>>>(act, w16, bA);
    bnfin_kernel<<<1, 128>>>(bn2g, bn2b, 64);

    // conv3 3x3 64->48 (hi/lo 3-pass)
    bnrelu_hl<64, 64><<<4096, 256>>>(bA, act);
    w16prep_hl<<<144, 256>>>(conv3w, w16, 9, 64, 64, 48, 64);
    cudaMemsetAsync(pstats, 0, sizeof(g_stats));
    c3<<<1024, 256, SM2>>>(act, w16, bB);
    bnfin_kernel<<<1, 128>>>(bn3g, bn3b, 48);

    // obj1 3x3 48->48 (hi/lo 3-pass)
    bnrelu_hl<48, 64><<<4096, 256>>>(bB, act);
    w16prep_hl<<<144, 256>>>(obj1w, w16, 9, 64, 64, 48, 48);
    cudaMemsetAsync(pstats, 0, sizeof(g_stats));
    c3<<<1024, 256, SM2>>>(act, w16, bA);
    bnfin_kernel<<<1, 128>>>(bn4g, bn4b, 48);

    // obj2 1x1 48->20 + bias (fused bn4+relu)
    obj2_kernel<<<512, 256>>>(bA, obj2w, obj2b, out);
}

// round 6
// speedup vs baseline: 3.9488x; 1.1652x over previous
#include <cuda_runtime.h>
#include <cuda_fp16.h>
#include <cstdint>

#define EGO   64
#define MEM   128
#define NOBJ  20
#define HW    65536     // 256*256
#define NPIX  131072    // 2 * HW
#define NB    2
#define TT    4

typedef unsigned long long u64;

// ---------------- packed f32x2 helpers ----------------
__device__ __forceinline__ u64 bcast2(float x) {
    u64 r; asm("mov.b64 %0, {%1, %1};" : "=l"(r) : "f"(x)); return r;
}
__device__ __forceinline__ u64 pack2f(float x, float y) {
    u64 r; asm("mov.b64 %0, {%1, %2};" : "=l"(r) : "f"(x), "f"(y)); return r;
}
__device__ __forceinline__ u64 ffma2(u64 a, u64 b, u64 c) {
    u64 d; asm("fma.rn.f32x2 %0, %1, %2, %3;" : "=l"(d) : "l"(a), "l"(b), "l"(c)); return d;
}
__device__ __forceinline__ float2 unpk(u64 a) {
    float2 f; asm("mov.b64 {%0, %1}, %2;" : "=f"(f.x), "=f"(f.y) : "l"(a)); return f;
}

// ---------------- fast transcendentals ----------------
__device__ __forceinline__ float fast_sigmoid(float x) {
    float e; asm("ex2.approx.f32 %0, %1;" : "=f"(e) : "f"(-1.4426950408889634f * x));
    float r; asm("rcp.approx.f32 %0, %1;" : "=f"(r) : "f"(1.f + e));
    return r;
}
__device__ __forceinline__ float fast_tanh(float x) {
    float e; asm("ex2.approx.f32 %0, %1;" : "=f"(e) : "f"(2.8853900817779268f * x));
    float r; asm("rcp.approx.f32 %0, %1;" : "=f"(r) : "f"(1.f + e));
    return 1.f - 2.f * r;
}

// ---------------- smem / swizzle / mma helpers ----------------
__device__ __forceinline__ uint32_t smem_u32(const void* p) {
    uint32_t a; asm("{ .reg .u64 t; cvta.to.shared.u64 t, %1; cvt.u32.u64 %0, t; }" : "=r"(a) : "l"(p));
    return a;
}
#define SW128(o) ((o) ^ (((o) >> 3) & 0x70))

__device__ __forceinline__ void ldsm_x4(uint32_t& r0, uint32_t& r1, uint32_t& r2, uint32_t& r3,
                                        uint32_t addr) {
    asm volatile("ldmatrix.sync.aligned.m8n8.x4.shared.b16 {%0,%1,%2,%3}, [%4];"
                 : "=r"(r0), "=r"(r1), "=r"(r2), "=r"(r3) : "r"(addr));
}
__device__ __forceinline__ void mma16816(float* c, const uint32_t* a, uint32_t b0, uint32_t b1) {
    asm volatile(
        "mma.sync.aligned.m16n8k16.row.col.f32.f16.f16.f32 "
        "{%0,%1,%2,%3}, {%4,%5,%6,%7}, {%8,%9}, {%0,%1,%2,%3};"
        : "+f"(c[0]), "+f"(c[1]), "+f"(c[2]), "+f"(c[3])
        : "r"(a[0]), "r"(a[1]), "r"(a[2]), "r"(a[3]), "r"(b0), "r"(b1));
}

// ---------------- static scratch ----------------
__device__ __half g_hA[(size_t)NPIX * 128];
__device__ __half g_hB[(size_t)NPIX * 128];
__device__ __half g_act16[(size_t)NPIX * 256];
__device__ float  g_bufA[(size_t)NPIX * 128];
__device__ float  g_bufB[(size_t)NPIX * 128];
__device__ __half g_w16[49 * 128 * 128];
__device__ __half g_w16g[4 * 3 * 128 * 64];
__device__ int    g_any[8];
__device__ float  g_stats[256];
__device__ float  g_scale[128];
__device__ float  g_shift[128];

// ---------------- any / observed ----------------
__global__ void any_kernel(const int* __restrict__ masks) {
    int idx = blockIdx.x * blockDim.x + threadIdx.x;
    int v = masks[idx];
    unsigned b = __ballot_sync(0xffffffffu, v > 0);
    if ((threadIdx.x & 31) == 0 && b)
        atomicOr(&g_any[idx >> 16], 1);
}
__global__ void obs_kernel(const int* __restrict__ masks, float* __restrict__ outobs) {
    int idx = blockIdx.x * blockDim.x + threadIdx.x;
    int n = idx >> 16, pix = idx & 65535;
    int s = 0;
#pragma unroll
    for (int t = 0; t < TT; ++t)
        s += masks[((n * TT + t) << 16) + pix] * g_any[n * TT + t];
    outobs[idx] = (float)s;
}

// ---------------- GRU weight prep ----------------
__global__ void w16gru_prep(const float* __restrict__ wih, const float* __restrict__ whh,
                            __half* __restrict__ o) {
    int i = blockIdx.x * 256 + threadIdx.x;
    if (i >= 4 * 3 * 128 * 64) return;
    int bb = i / 24576; int r = i - bb * 24576;
    int c  = r / 8192;  int r2 = r - c * 8192;
    int row = r2 >> 6;  int kk = r2 & 63;
    int ul = row >> 2, g4 = row & 3;
    int gu = bb * 32 + ul;
    float v = 0.f;
    if (g4 == 0)      v = (c == 0) ? wih[(      gu) * 64 + kk] : whh[(      gu) * 128 + (c - 1) * 64 + kk];
    else if (g4 == 1) v = (c == 0) ? wih[(128 + gu) * 64 + kk] : whh[(128 + gu) * 128 + (c - 1) * 64 + kk];
    else if (g4 == 2) v = (c == 0) ? wih[(256 + gu) * 64 + kk] : 0.f;
    else              v = (c == 0) ? 0.f : whh[(256 + gu) * 128 + (c - 1) * 64 + kk];
    o[i] = __float2half_rn(v);
}

// ---------------- GRU step via HMMA (as R5) ----------------
#define GRU_SMEM (81920 + 768 + 32 + 512 + 512)

template<bool FIRST>
__global__ __launch_bounds__(256, 2) void gru_hmma(
    const float* __restrict__ feats, const int* __restrict__ masks,
    const __half* __restrict__ w16g,
    const float* __restrict__ b_ih, const float* __restrict__ b_hh,
    const __half* __restrict__ hin, __half* __restrict__ hout, int t)
{
    extern __shared__ char sm[];
    float* gbuf = (float*)sm;
    float* sbias = (float*)(sm + 81920);
    int* wcnt  = (int*)(sm + 81920 + 768);
    int* cnts  = (int*)(sm + 81920 + 768 + 16);
    int* clist = (int*)(sm + 81920 + 768 + 32);
    int* ulist = (int*)(sm + 81920 + 768 + 32 + 512);

    int tid = threadIdx.x;
    int lane = tid & 31, wrp = tid >> 5;
    int mw = wrp >> 1, nw = wrp & 1;
    int p0 = blockIdx.x * 128;
    int bb = blockIdx.y;
    int ub = bb * 32;
    int n = p0 >> 16, pix0 = p0 & 65535;

    const int* mrow = masks + ((size_t)(n * TT + t) << 16) + pix0;

    int mv = 0; unsigned bal = 0; int posm = 0;
    if (tid < 128) {
        mv = mrow[tid] > 0;
        bal = __ballot_sync(0xffffffffu, mv);
        posm = __popc(bal & ((1u << lane) - 1));
        if (lane == 0) wcnt[tid >> 5] = __popc(bal);
    }
    if (tid < 96) {
        int g = tid >> 5, u = tid & 31;
        sbias[tid] = b_ih[g * 128 + ub + u];
    } else if (tid < 192) {
        int t2 = tid - 96;
        int g = t2 >> 5, u = t2 & 31;
        sbias[tid] = b_hh[g * 128 + ub + u];
    }
    __syncthreads();
    if (tid < 128) {
        int w = tid >> 5;
        int off = 0;
#pragma unroll
        for (int j = 0; j < 4; ++j) if (j < w) off += wcnt[j];
        if (mv) clist[off + posm] = tid;
        else    ulist[32 * w - off + lane - posm] = tid;
        if (tid == 0) cnts[0] = wcnt[0] + wcnt[1] + wcnt[2] + wcnt[3];
    }

    const int CH = FIRST ? 1 : 3;
    int px = tid >> 1, sg = tid & 1;

    {
        int sr = tid >> 1, h2 = tid & 1;
        for (int c = 0; c < CH; ++c) {
            const __half* src = w16g + ((size_t)((bb * 3 + c) * 128 + sr)) * 64 + h2 * 32;
            char* base = sm + 32768 + c * 16384;
#pragma unroll
            for (int j = 0; j < 4; ++j) {
                uint4 v = *(const uint4*)(src + j * 8);
                uint32_t bo = (uint32_t)sr * 128 + h2 * 64 + j * 16;
                *(uint4*)(base + SW128(bo)) = v;
            }
        }
    }

    auto stageA = [&](int c, int slot) {
        char* base = sm + slot * 16384;
        if (c == 0) {
            const float* src = feats + ((size_t)(n * TT + t) * HW + pix0 + px) * 64 + sg * 32;
#pragma unroll
            for (int j = 0; j < 4; ++j) {
                float4 a = *(const float4*)(src + j * 8);
                float4 b = *(const float4*)(src + j * 8 + 4);
                __half2 h[4] = { __floats2half2_rn(a.x, a.y), __floats2half2_rn(a.z, a.w),
                                 __floats2half2_rn(b.x, b.y), __floats2half2_rn(b.z, b.w) };
                uint32_t bo = (uint32_t)px * 128 + sg * 64 + j * 16;
                *(uint4*)(base + SW128(bo)) = *(const uint4*)h;
            }
        } else {
            const __half* src = hin + ((size_t)(p0 + px)) * 128 + (c - 1) * 64 + sg * 32;
#pragma unroll
            for (int j = 0; j < 4; ++j) {
                uint4 v = *(const uint4*)(src + j * 8);
                uint32_t bo = (uint32_t)px * 128 + sg * 64 + j * 16;
                *(uint4*)(base + SW128(bo)) = v;
            }
        }
    };

    float acc[2][8][4];
#pragma unroll
    for (int mi = 0; mi < 2; ++mi)
#pragma unroll
        for (int nj = 0; nj < 8; ++nj)
#pragma unroll
            for (int e = 0; e < 4; ++e) acc[mi][nj][e] = 0.f;

    stageA(0, 0);
    __syncthreads();

    for (int c = 0; c < CH; ++c) {
        int slot = c & 1;
        if (c + 1 < CH) stageA(c + 1, slot ^ 1);

        uint32_t abase = smem_u32(sm + slot * 16384);
        uint32_t bbase = smem_u32(sm + 32768 + c * 16384);
#pragma unroll
        for (int kk = 0; kk < 4; ++kk) {
            uint32_t bo = kk * 32 + ((lane >> 4) << 4);
            uint32_t afr[2][4];
#pragma unroll
            for (int mi = 0; mi < 2; ++mi) {
                uint32_t row = mw * 32 + mi * 16 + (lane & 15);
                ldsm_x4(afr[mi][0], afr[mi][1], afr[mi][2], afr[mi][3],
                        abase + SW128(row * 128 + bo));
            }
#pragma unroll
            for (int ni = 0; ni < 4; ++ni) {
                uint32_t row = nw * 64 + ni * 16 + (lane & 15);
                uint32_t b0, b1, b2, b3;
                ldsm_x4(b0, b1, b2, b3, bbase + SW128(row * 128 + bo));
#pragma unroll
                for (int mi = 0; mi < 2; ++mi) {
                    mma16816(acc[mi][ni * 2],     afr[mi], b0, b2);
                    mma16816(acc[mi][ni * 2 + 1], afr[mi], b1, b3);
                }
            }
        }
        __syncthreads();
    }

#pragma unroll
    for (int mi = 0; mi < 2; ++mi)
#pragma unroll
        for (int nj = 0; nj < 8; ++nj) {
            int row = mw * 32 + mi * 16 + (lane >> 2);
            int col = nw * 64 + nj * 8 + (lane & 3) * 2;
            *(float2*)&gbuf[row * 132 + col]       = make_float2(acc[mi][nj][0], acc[mi][nj][1]);
            *(float2*)&gbuf[(row + 8) * 132 + col] = make_float2(acc[mi][nj][2], acc[mi][nj][3]);
        }
    __syncthreads();

    int cnt = cnts[0];
    for (int i = tid; i < 2 * cnt; i += 256) {
        int pxl = clist[i >> 1];
        int half = i & 1;
        __half hold[16];
        if (!FIRST) {
            const __half* hp = hin + ((size_t)(p0 + pxl)) * 128 + ub + half * 16;
            *(uint4*)&hold[0] = *(const uint4*)hp;
            *(uint4*)&hold[8] = *(const uint4*)(hp + 8);
        }
        __half hnew[16];
#pragma unroll
        for (int u = 0; u < 16; ++u) {
            int ul = half * 16 + u;
            float4 g = *(float4*)&gbuf[pxl * 132 + ul * 4];
            float r = fast_sigmoid(g.x + sbias[ul] + sbias[96 + ul]);
            float z = fast_sigmoid(g.y + sbias[32 + ul] + sbias[128 + ul]);
            float nv = fast_tanh(g.z + sbias[64 + ul] + r * (g.w + sbias[160 + ul]));
            float ho = FIRST ? 0.f : __half2float(hold[u]);
            float hv = nv + z * (ho - nv);
            hnew[u] = __float2half_rn(hv);
        }
        __half* op = hout + ((size_t)(p0 + pxl)) * 128 + ub + half * 16;
        *(uint4*)op       = *(const uint4*)&hnew[0];
        *(uint4*)(op + 8) = *(const uint4*)&hnew[8];
    }
    int un = 128 - cnt;
    for (int i = tid; i < 2 * un; i += 256) {
        int pxl = ulist[i >> 1];
        int half = i & 1;
        __half* op = hout + ((size_t)(p0 + pxl)) * 128 + ub + half * 16;
        if (FIRST) {
            uint4 z = make_uint4(0, 0, 0, 0);
            *(uint4*)op = z; *(uint4*)(op + 8) = z;
        } else {
            const __half* hp = hin + ((size_t)(p0 + pxl)) * 128 + ub + half * 16;
            *(uint4*)op       = *(const uint4*)hp;
            *(uint4*)(op + 8) = *(const uint4*)(hp + 8);
        }
    }
}

// ---------------- bn+relu f32 -> hi/lo fp16 ----------------
template<int CIN, int CHI>
__global__ void bnrelu_hl(const float* __restrict__ in, __half* __restrict__ out) {
    int i = blockIdx.x * 256 + threadIdx.x;
    int px = i / (CHI / 8);
    int c0 = (i % (CHI / 8)) * 8;
    __half2 hi[4], lo[4];
#pragma unroll
    for (int j = 0; j < 4; ++j) {
        int c = c0 + 2 * j;
        float v0 = 0.f, v1 = 0.f;
        if (c < CIN) {
            float2 v = *(const float2*)(in + (size_t)px * CIN + c);
            v0 = fmaxf(v.x * g_scale[c] + g_shift[c], 0.f);
            v1 = fmaxf(v.y * g_scale[c + 1] + g_shift[c + 1], 0.f);
        }
        __half h0 = __float2half_rn(v0), h1 = __float2half_rn(v1);
        hi[j] = __halves2half2(h0, h1);
        lo[j] = __floats2half2_rn(v0 - __half2float(h0), v1 - __half2float(h1));
    }
    *(uint4*)(out + (size_t)px * (2 * CHI) + c0)       = *(const uint4*)hi;
    *(uint4*)(out + (size_t)px * (2 * CHI) + CHI + c0) = *(const uint4*)lo;
}

// ---------------- weight prep ----------------
__global__ void w16prep(const float* __restrict__ w, __half* __restrict__ o,
                        int NTAP, int OCT, int ICP, int Cout, int Cin) {
    int i = blockIdx.x * 256 + threadIdx.x;
    if (i >= NTAP * OCT * ICP) return;
    int tap = i / (OCT * ICP);
    int r = i - tap * (OCT * ICP);
    int oc = r / ICP, ic = r - oc * ICP;
    float v = (oc < Cout && ic < Cin) ? w[((size_t)oc * Cin + ic) * NTAP + tap] : 0.f;
    o[i] = __float2half_rn(v);
}
__global__ void w16prep_hl(const float* __restrict__ w, __half* __restrict__ o,
                           int NTAP, int OCT, int ICP, int Cout, int Cin) {
    int i = blockIdx.x * 256 + threadIdx.x;
    if (i >= NTAP * OCT * ICP) return;
    int tap = i / (OCT * ICP);
    int r = i - tap * (OCT * ICP);
    int oc = r / ICP, ic = r - oc * ICP;
    float v = (oc < Cout && ic < Cin) ? w[((size_t)oc * Cin + ic) * NTAP + tap] : 0.f;
    __half h = __float2half_rn(v);
    size_t base = ((size_t)tap * OCT + oc) * (2 * ICP);
    o[base + ic] = h;
    o[base + ICP + ic] = __float2half_rn(v - __half2float(h));
}

// ---------------- HMMA implicit-GEMM conv, kx-shared A staging --------------
// A smem: halo'd row window [RWIN = 128+2*PAD rows][64 ic halves] per (ky, chunk).
// All K kx-taps consume one A stage at row offset +kx. B restaged per substage.
template<int K, int ICH, int CINP, int OCT, int COUT, int PHASES>
__global__ __launch_bounds__(256) void conv_hmma(
    const __half* __restrict__ in, const __half* __restrict__ w16,
    float* __restrict__ out)
{
    constexpr int PAD = K / 2;
    constexpr int RWIN = 128 + 2 * PAD;
    constexpr int NS = K * K * PHASES * ICH;       // substages (B stages)
    constexpr int BW = (PHASES == 3 ? 2 : 1) * ICH * 64;
    constexpr int ABYTES = RWIN * 128;
    constexpr int BBYTES = OCT * 128;
    constexpr int NJ = OCT / 16;
    constexpr int NI2 = NJ / 2;
    constexpr int BLK = K * PHASES;                // substages per (ky, i)
    constexpr int BPER = (OCT * 8) / 256;          // uint4 per thread for B stage

    extern __shared__ __align__(16) char sm[];
    char* ab[2] = { sm, sm + ABYTES };
    char* bb[2] = { sm + 2 * ABYTES, sm + 2 * ABYTES + BBYTES };
    float* sacc = (float*)(sm + 2 * ABYTES + 2 * BBYTES);
    float* qacc = sacc + OCT;

    int tid = threadIdx.x;
    int lane = tid & 31, wrp = tid >> 5;
    int mw = wrp >> 1, nw = wrp & 1;
    int p0 = blockIdx.x * 128;
    int n = p0 >> 16;
    int y = (p0 >> 8) & 255;
    int x0 = p0 & 255;

    float acc[2][NJ][4];
#pragma unroll
    for (int mi = 0; mi < 2; ++mi)
#pragma unroll
        for (int nj = 0; nj < NJ; ++nj)
#pragma unroll
            for (int e = 0; e < 4; ++e) acc[mi][nj][e] = 0.f;

    // ---- decode helpers ----
    auto decode = [&](int s, int& ky, int& aoff, int& boff, int& kx, int& a_id) {
        int t0 = s / (BLK * ICH);
        int t1 = s - t0 * BLK * ICH;
        int i  = t1 / BLK;
        int u  = t1 - i * BLK;
        int seg = u / K;
        kx = u - seg * K;
        ky = t0;
        aoff = (seg == 2) ? ICH + i : i;
        boff = (seg == 1) ? ICH + i : i;
        a_id = (PHASES == 3) ? ((t0 * ICH + i) * 2 + (seg == 2 ? 1 : 0))
                             : (t0 * ICH + i);
    };

    // ---- staging ----
    auto stageA = [&](int ky, int aoff, int slot) {
        char* base = ab[slot];
        int gy = y + ky - PAD;
        int hh = tid & 1;
        for (int r = tid >> 1; r < RWIN; r += 128) {
            int gx = x0 + r - PAD;
            uint4 v[4] = { {0,0,0,0}, {0,0,0,0}, {0,0,0,0}, {0,0,0,0} };
            if ((unsigned)gy < 256u && (unsigned)gx < 256u) {
                const uint4* src = (const uint4*)(in +
                    ((size_t)((n * 256 + gy) * 256 + gx)) * CINP + aoff * 64 + hh * 32);
#pragma unroll
                for (int j = 0; j < 4; ++j) v[j] = src[j];
            }
#pragma unroll
            for (int j = 0; j < 4; ++j) {
                uint32_t bo = (uint32_t)r * 128 + hh * 64 + j * 16;
                *(uint4*)(base + SW128(bo)) = v[j];
            }
        }
    };
    auto stageB = [&](int tap, int boff, int slot) {
        char* base = bb[slot];
#pragma unroll
        for (int j = 0; j < BPER; ++j) {
            int idx = tid * BPER + j;
            int row = idx >> 3, q = idx & 7;
            uint4 v = *(const uint4*)(w16 + ((size_t)tap * OCT + row) * BW + boff * 64 + q * 8);
            uint32_t bo = (uint32_t)row * 128 + q * 16;
            *(uint4*)(base + SW128(bo)) = v;
        }
    };

    // prologue: stage A0, B0
    {
        int ky, aoff, boff, kx, a_id;
        decode(0, ky, aoff, boff, kx, a_id);
        stageA(ky, aoff, 0);
        stageB(ky * K + kx, boff, 0);
    }
    __syncthreads();

    int ky, aoff, boff, kx, a_id;
    decode(0, ky, aoff, boff, kx, a_id);

    for (int s = 0; s < NS; ++s) {
        // prefetch s+1
        if (s + 1 < NS) {
            int ky2, aoff2, boff2, kx2, a_id2;
            decode(s + 1, ky2, aoff2, boff2, kx2, a_id2);
            stageB(ky2 * K + kx2, boff2, (s + 1) & 1);
            if (a_id2 != a_id) stageA(ky2, aoff2, a_id2 & 1);
            // consume current
            uint32_t abase = smem_u32(ab[a_id & 1]);
            uint32_t bbase = smem_u32(bb[s & 1]);
#pragma unroll
            for (int kk = 0; kk < 4; ++kk) {
                uint32_t bo = kk * 32 + ((lane >> 4) << 4);
                uint32_t afr[2][4];
#pragma unroll
                for (int mi = 0; mi < 2; ++mi) {
                    uint32_t row = mw * 32 + mi * 16 + (lane & 15) + kx;
                    ldsm_x4(afr[mi][0], afr[mi][1], afr[mi][2], afr[mi][3],
                            abase + SW128(row * 128 + bo));
                }
#pragma unroll
                for (int ni = 0; ni < NI2; ++ni) {
                    uint32_t row = nw * (OCT / 2) + ni * 16 + (lane & 15);
                    uint32_t b0, b1, b2, b3;
                    ldsm_x4(b0, b1, b2, b3, bbase + SW128(row * 128 + bo));
#pragma unroll
                    for (int mi = 0; mi < 2; ++mi) {
                        mma16816(acc[mi][ni * 2],     afr[mi], b0, b2);
                        mma16816(acc[mi][ni * 2 + 1], afr[mi], b1, b3);
                    }
                }
            }
            ky = ky2; aoff = aoff2; boff = boff2; kx = kx2; a_id = a_id2;
        } else {
            uint32_t abase = smem_u32(ab[a_id & 1]);
            uint32_t bbase = smem_u32(bb[s & 1]);
#pragma unroll
            for (int kk = 0; kk < 4; ++kk) {
                uint32_t bo = kk * 32 + ((lane >> 4) << 4);
                uint32_t afr[2][4];
#pragma unroll
                for (int mi = 0; mi < 2; ++mi) {
                    uint32_t row = mw * 32 + mi * 16 + (lane & 15) + kx;
                    ldsm_x4(afr[mi][0], afr[mi][1], afr[mi][2], afr[mi][3],
                            abase + SW128(row * 128 + bo));
                }
#pragma unroll
                for (int ni = 0; ni < NI2; ++ni) {
                    uint32_t row = nw * (OCT / 2) + ni * 16 + (lane & 15);
                    uint32_t b0, b1, b2, b3;
                    ldsm_x4(b0, b1, b2, b3, bbase + SW128(row * 128 + bo));
#pragma unroll
                    for (int mi = 0; mi < 2; ++mi) {
                        mma16816(acc[mi][ni * 2],     afr[mi], b0, b2);
                        mma16816(acc[mi][ni * 2 + 1], afr[mi], b1, b3);
                    }
                }
            }
        }
        __syncthreads();
    }

    // ---- epilogue ----
    if (tid < OCT) { sacc[tid] = 0.f; qacc[tid] = 0.f; }
    __syncthreads();

#pragma unroll
    for (int nj = 0; nj < NJ; ++nj) {
        int col = nw * (OCT / 2) + nj * 8 + (lane & 3) * 2;
        if (col < COUT) {
            float s0 = 0.f, s1 = 0.f, q0 = 0.f, q1 = 0.f;
#pragma unroll
            for (int mi = 0; mi < 2; ++mi) {
                int row = mw * 32 + mi * 16 + (lane >> 2);
                float d0 = acc[mi][nj][0], d1 = acc[mi][nj][1];
                float d2 = acc[mi][nj][2], d3 = acc[mi][nj][3];
                *(float2*)(out + (size_t)(p0 + row) * COUT + col)     = make_float2(d0, d1);
                *(float2*)(out + (size_t)(p0 + row + 8) * COUT + col) = make_float2(d2, d3);
                s0 += d0 + d2; s1 += d1 + d3;
                q0 += d0 * d0 + d2 * d2; q1 += d1 * d1 + d3 * d3;
            }
            atomicAdd(&sacc[col], s0);     atomicAdd(&sacc[col + 1], s1);
            atomicAdd(&qacc[col], q0);     atomicAdd(&qacc[col + 1], q1);
        }
    }
    __syncthreads();
    if (tid < OCT && tid < COUT) {
        atomicAdd(&g_stats[tid], sacc[tid]);
        atomicAdd(&g_stats[128 + tid], qacc[tid]);
    }
}

// ---------------- BN finalize ----------------
__global__ void bnfin_kernel(const float* __restrict__ g, const float* __restrict__ b, int C) {
    int c = threadIdx.x;
    if (c < C) {
        float inv = 1.f / (float)NPIX;
        float mu  = g_stats[c] * inv;
        float var = g_stats[128 + c] * inv - mu * mu;
        float sc  = g[c] * rsqrtf(var + 1e-5f);
        g_scale[c] = sc;
        g_shift[c] = b[c] - mu * sc;
    }
}

// ---------------- obj2 1x1 (48->20) ----------------
__global__ __launch_bounds__(256) void obj2_kernel(
    const float* __restrict__ in, const float* __restrict__ w,
    const float* __restrict__ b, float* __restrict__ out)
{
    __shared__ float wst[48 * 20];
    __shared__ float bs[20];
    int tid = threadIdx.x;
    for (int i = tid; i < 48 * 20; i += 256) {
        int o = i / 48, ic = i - o * 48;
        wst[ic * 20 + o] = w[o * 48 + ic];
    }
    if (tid < 20) bs[tid] = b[tid];
    __syncthreads();

    int p = blockIdx.x * 256 + tid;
    int n = p >> 16, pix = p & 65535;
    const float* ip = in + (size_t)p * 48;
    u64 accp[10];
#pragma unroll
    for (int o = 0; o < 10; ++o) accp[o] = pack2f(bs[2 * o], bs[2 * o + 1]);
#pragma unroll
    for (int ic = 0; ic < 48; ++ic) {
        float v = fmaxf(ip[ic] * g_scale[ic] + g_shift[ic], 0.f);
        u64 vb = bcast2(v);
#pragma unroll
        for (int o = 0; o < 10; ++o) {
            u64 wp = *(const u64*)&wst[ic * 20 + 2 * o];
            accp[o] = ffma2(wp, vb, accp[o]);
        }
    }
#pragma unroll
    for (int o = 0; o < 10; ++o) {
        float2 f = unpk(accp[o]);
        out[((size_t)(n * NOBJ + 2 * o)     << 16) + pix] = f.x;
        out[((size_t)(n * NOBJ + 2 * o + 1) << 16) + pix] = f.y;
    }
}

// ---------------- launch ----------------
extern "C" void kernel_launch(void* const* d_in, const int* in_sizes, int n_in,
                              void* d_out, int out_size)
{
    const float* feats  = (const float*)d_in[0];
    const int*   masks  = (const int*)  d_in[1];
    const float* w_ih   = (const float*)d_in[2];
    const float* w_hh   = (const float*)d_in[3];
    const float* b_ih   = (const float*)d_in[4];
    const float* b_hh   = (const float*)d_in[5];
    const float* conv1w = (const float*)d_in[6];
    const float* bn1g   = (const float*)d_in[7];
    const float* bn1b   = (const float*)d_in[8];
    const float* conv2w = (const float*)d_in[9];
    const float* bn2g   = (const float*)d_in[10];
    const float* bn2b   = (const float*)d_in[11];
    const float* conv3w = (const float*)d_in[12];
    const float* bn3g   = (const float*)d_in[13];
    const float* bn3b   = (const float*)d_in[14];
    const float* obj1w  = (const float*)d_in[15];
    const float* bn4g   = (const float*)d_in[16];
    const float* bn4b   = (const float*)d_in[17];
    const float* obj2w  = (const float*)d_in[18];
    const float* obj2b  = (const float*)d_in[19];
    float* out = (float*)d_out;

    void *pany, *pstats, *pbA, *pbB, *phA, *phB, *pact, *pw16, *pw16g;
    cudaGetSymbolAddress(&pany, g_any);
    cudaGetSymbolAddress(&pstats, g_stats);
    cudaGetSymbolAddress(&pbA, g_bufA);
    cudaGetSymbolAddress(&pbB, g_bufB);
    cudaGetSymbolAddress(&phA, g_hA);
    cudaGetSymbolAddress(&phB, g_hB);
    cudaGetSymbolAddress(&pact, g_act16);
    cudaGetSymbolAddress(&pw16, g_w16);
    cudaGetSymbolAddress(&pw16g, g_w16g);
    float* bA = (float*)pbA;
    float* bB = (float*)pbB;
    __half* hA = (__half*)phA;
    __half* hB = (__half*)phB;
    __half* act = (__half*)pact;
    __half* w16 = (__half*)pw16;
    __half* w16g = (__half*)pw16g;

    auto* g0 = gru_hmma<true>;
    auto* g1 = gru_hmma<false>;
    auto* c1 = conv_hmma<7, 2, 128, 128, 128, 1>;
    auto* c2 = conv_hmma<3, 2, 256, 64, 64, 3>;
    auto* c3 = conv_hmma<3, 1, 128, 64, 48, 3>;
    const int SM1 = 2 * (134 * 128) + 2 * 16384 + 128 * 8;   // 68352
    const int SM2 = 2 * (130 * 128) + 2 * 8192 + 64 * 8;     // 50176
    cudaFuncSetAttribute(g0, cudaFuncAttributeMaxDynamicSharedMemorySize, GRU_SMEM);
    cudaFuncSetAttribute(g1, cudaFuncAttributeMaxDynamicSharedMemorySize, GRU_SMEM);
    cudaFuncSetAttribute(c1, cudaFuncAttributeMaxDynamicSharedMemorySize, SM1);
    cudaFuncSetAttribute(c2, cudaFuncAttributeMaxDynamicSharedMemorySize, SM2);
    cudaFuncSetAttribute(c3, cudaFuncAttributeMaxDynamicSharedMemorySize, SM2);

    cudaMemsetAsync(pany, 0, sizeof(g_any));
    any_kernel<<<2048, 256>>>(masks);
    obs_kernel<<<512, 256>>>(masks, out + (size_t)NB * NOBJ * HW);

    w16gru_prep<<<384, 256>>>(w_ih, w_hh, w16g);
    w16prep<<<3136, 256>>>(conv1w, w16, 49, 128, 128, 128, 128);

    dim3 ggrid(1024, 4);
    g0<<<ggrid, 256, GRU_SMEM>>>(feats, masks, w16g, b_ih, b_hh, hA, hA, 0);
    g1<<<ggrid, 256, GRU_SMEM>>>(feats, masks, w16g, b_ih, b_hh, hA, hB, 1);
    g1<<<ggrid, 256, GRU_SMEM>>>(feats, masks, w16g, b_ih, b_hh, hB, hA, 2);
    g1<<<ggrid, 256, GRU_SMEM>>>(feats, masks, w16g, b_ih, b_hh, hA, hB, 3);

    // conv1 7x7 128->128 (single fp16)
    cudaMemsetAsync(pstats, 0, sizeof(g_stats));
    c1<<<1024, 256, SM1>>>(hB, w16, bB);
    bnfin_kernel<<<1, 128>>>(bn1g, bn1b, 128);

    // conv2 3x3 128->64 (hi/lo 3-pass)
    bnrelu_hl<128, 128><<<8192, 256>>>(bB, act);
    w16prep_hl<<<288, 256>>>(conv2w, w16, 9, 64, 128, 64, 128);
    cudaMemsetAsync(pstats, 0, sizeof(g_stats));
    c2<<<1024, 256, SM2>>>(act, w16, bA);
    bnfin_kernel<<<1, 128>>>(bn2g, bn2b, 64);

    // conv3 3x3 64->48 (hi/lo 3-pass)
    bnrelu_hl<64, 64><<<4096, 256>>>(bA, act);
    w16prep_hl<<<144, 256>>>(conv3w, w16, 9, 64, 64, 48, 64);
    cudaMemsetAsync(pstats, 0, sizeof(g_stats));
    c3<<<1024, 256, SM2>>>(act, w16, bB);
    bnfin_kernel<<<1, 128>>>(bn3g, bn3b, 48);

    // obj1 3x3 48->48 (hi/lo 3-pass)
    bnrelu_hl<48, 64><<<4096, 256>>>(bB, act);
    w16prep_hl<<<144, 256>>>(obj1w, w16, 9, 64, 64, 48, 48);
    cudaMemsetAsync(pstats, 0, sizeof(g_stats));
    c3<<<1024, 256, SM2>>>(act, w16, bA);
    bnfin_kernel<<<1, 128>>>(bn4g, bn4b, 48);

    obj2_kernel<<<512, 256>>>(bA, obj2w, obj2b, out);
}